// round 4
// baseline (speedup 1.0000x reference)
#include <cuda_runtime.h>
#include <cstddef>

// ---------------------------------------------------------------------------
// Problem constants
// ---------------------------------------------------------------------------
#define BATCH 8
#define HH 64
#define WW 64
#define DIM1 384
#define DIM2 256
#define NHEAD 8
#define DHEAD 32
#define INNER 256
#define NTOK 32768            // BATCH*HH*WW
#define LN_EPS 1e-5f

// ---------------------------------------------------------------------------
// Scratch (static device allocation; runtime allocs are forbidden)
// ---------------------------------------------------------------------------
constexpr size_t OFF_MU1  = 0;
constexpr size_t OFF_RS1  = OFF_MU1 + NTOK;
constexpr size_t OFF_MU2  = OFF_RS1 + NTOK;
constexpr size_t OFF_RS2  = OFF_MU2 + NTOK;
constexpr size_t OFF_WSCT = OFF_RS2 + NTOK;                 // 384*256
constexpr size_t OFF_Q1   = OFF_WSCT + (size_t)DIM1 * DIM2;
constexpr size_t OFF_Q2   = OFF_Q1 + (size_t)NTOK * INNER;
constexpr size_t OFF_KV1  = OFF_Q2 + (size_t)NTOK * INNER;
constexpr size_t OFF_KV2  = OFF_KV1 + (size_t)NTOK * 2 * INNER;
constexpr size_t OFF_O1   = OFF_KV2 + (size_t)NTOK * 2 * INNER;
constexpr size_t OFF_O2   = OFF_O1 + (size_t)NTOK * INNER;
constexpr size_t OFF_ACC  = OFF_O2 + (size_t)NTOK * INNER;
constexpr size_t SCRATCH_TOTAL = OFF_ACC + (size_t)NTOK * INNER;

__device__ __align__(128) float g_scratch[SCRATCH_TOTAL];

// ---------------------------------------------------------------------------
// LayerNorm stats: per-token mean / rstd over channels (stride-4096 reads,
// coalesced across tokens)
// ---------------------------------------------------------------------------
__global__ void ln_stats_kernel(const float* __restrict__ x, int C,
                                float* __restrict__ mu, float* __restrict__ rs) {
    int m = blockIdx.x * blockDim.x + threadIdx.x;   // token id, 0..NTOK-1
    int b = m >> 12;
    int hw = m & 4095;
    const float* p = x + ((size_t)b * C << 12) + hw;
    float s = 0.f, s2 = 0.f;
    for (int c = 0; c < C; c++) {
        float v = p[(size_t)c << 12];
        s += v;
        s2 += v * v;
    }
    float invC = 1.0f / (float)C;
    float mean = s * invC;
    float var = s2 * invC - mean * mean;
    mu[m] = mean;
    rs[m] = rsqrtf(var + LN_EPS);
}

// ---------------------------------------------------------------------------
// Small transpose: Wsc [256,384] (out,in) -> WscT [384,256] (k,n)
// ---------------------------------------------------------------------------
__global__ void transpose_wsc_kernel(const float* __restrict__ Wsc,
                                     float* __restrict__ WT) {
    __shared__ float t[32][33];
    int k0 = blockIdx.x * 32;    // 0..383 (12 tiles)
    int n0 = blockIdx.y * 32;    // 0..255 (8 tiles)
    int tx = threadIdx.x, ty = threadIdx.y;   // 32 x 8
#pragma unroll
    for (int q = 0; q < 4; q++)
        t[ty + q * 8][tx] = Wsc[(size_t)(n0 + ty + q * 8) * DIM1 + k0 + tx];
    __syncthreads();
#pragma unroll
    for (int q = 0; q < 4; q++)
        WT[(size_t)(k0 + ty + q * 8) * DIM2 + n0 + tx] = t[tx][ty + q * 8];
}

// ---------------------------------------------------------------------------
// GEMM: C[M,N] = A[M,K] @ B[K,N]  (64x64 tile, 16 k-slice, 256 thr, 4x4 micro)
//   AMODE 0: A is NCHW tensor, A[m,k] = A[(b*K+k)*4096 + hw]  (m-contiguous)
//   AMODE 1: A row-major [M,K]
//   LNA:     apply (a - mu[m])*rs[m]*lnw[k] + lnb[k] on the A load
//   EPI 0:   C = result                      (C stride N)
//   EPI 1:   C = BN(result) + x2f[m,n]       (shortcut init of accumulator)
//   EPI 2:   C += result + bias[n]           (Wout accumulate)
// ---------------------------------------------------------------------------
template <int AMODE, int LNA, int EPI>
__global__ __launch_bounds__(256)
void gemm_kernel(const float* __restrict__ A, const float* __restrict__ Bw,
                 float* __restrict__ C, int N, int K,
                 const float* __restrict__ mu, const float* __restrict__ rs,
                 const float* __restrict__ lnw, const float* __restrict__ lnb,
                 const float* __restrict__ bias,
                 const float* __restrict__ bng, const float* __restrict__ bnb,
                 const float* __restrict__ bnm, const float* __restrict__ bnv,
                 const float* __restrict__ xadd) {
    __shared__ float As[16][68];
    __shared__ float Bs[16][68];

    const int tid = threadIdx.x;
    const int tx = tid & 15;
    const int ty = tid >> 4;
    const int m0 = blockIdx.x * 64;
    const int n0 = blockIdx.y * 64;
    const int bI = m0 >> 12;     // image index (AMODE 0)
    const int hw0 = m0 & 4095;

    float acc[4][4];
#pragma unroll
    for (int i = 0; i < 4; i++)
#pragma unroll
        for (int j = 0; j < 4; j++) acc[i][j] = 0.f;

    for (int k0 = 0; k0 < K; k0 += 16) {
        // --- load A tile ---
        if (AMODE == 0) {
#pragma unroll
            for (int l = 0; l < 4; l++) {
                int idx = tid + l * 256;
                int ml = idx & 63;
                int kk = idx >> 6;
                int kg = k0 + kk;
                float v = A[(((size_t)(bI * K + kg)) << 12) + hw0 + ml];
                if (LNA) {
                    int mg = m0 + ml;
                    v = (v - mu[mg]) * rs[mg] * lnw[kg] + lnb[kg];
                }
                As[kk][ml] = v;
            }
        } else {
            int ml = tid >> 2;
            int kq = (tid & 3) * 4;
            float4 v = *reinterpret_cast<const float4*>(
                &A[(size_t)(m0 + ml) * K + k0 + kq]);
            As[kq + 0][ml] = v.x;
            As[kq + 1][ml] = v.y;
            As[kq + 2][ml] = v.z;
            As[kq + 3][ml] = v.w;
        }
        // --- load B tile ---
#pragma unroll
        for (int l = 0; l < 4; l++) {
            int idx = tid + l * 256;
            int nl = idx & 63;
            int kk = idx >> 6;
            Bs[kk][nl] = Bw[(size_t)(k0 + kk) * N + n0 + nl];
        }
        __syncthreads();
        // --- compute ---
#pragma unroll
        for (int kk = 0; kk < 16; kk++) {
            float4 a4 = *reinterpret_cast<const float4*>(&As[kk][ty * 4]);
            float4 b4 = *reinterpret_cast<const float4*>(&Bs[kk][tx * 4]);
            float av[4] = {a4.x, a4.y, a4.z, a4.w};
            float bv[4] = {b4.x, b4.y, b4.z, b4.w};
#pragma unroll
            for (int i = 0; i < 4; i++)
#pragma unroll
                for (int j = 0; j < 4; j++) acc[i][j] += av[i] * bv[j];
        }
        __syncthreads();
    }

    // --- epilogue ---
    const int nb = n0 + tx * 4;
    if (EPI == 0) {
#pragma unroll
        for (int i = 0; i < 4; i++) {
            int mg = m0 + ty * 4 + i;
            float4 v = make_float4(acc[i][0], acc[i][1], acc[i][2], acc[i][3]);
            *reinterpret_cast<float4*>(&C[(size_t)mg * N + nb]) = v;
        }
    } else if (EPI == 1) {
        float4 g4 = *reinterpret_cast<const float4*>(&bng[nb]);
        float4 b4 = *reinterpret_cast<const float4*>(&bnb[nb]);
        float4 m4 = *reinterpret_cast<const float4*>(&bnm[nb]);
        float4 v4 = *reinterpret_cast<const float4*>(&bnv[nb]);
        float sc[4], sb[4];
        sc[0] = rsqrtf(v4.x + LN_EPS) * g4.x; sb[0] = b4.x - m4.x * sc[0];
        sc[1] = rsqrtf(v4.y + LN_EPS) * g4.y; sb[1] = b4.y - m4.y * sc[1];
        sc[2] = rsqrtf(v4.z + LN_EPS) * g4.z; sb[2] = b4.z - m4.z * sc[2];
        sc[3] = rsqrtf(v4.w + LN_EPS) * g4.w; sb[3] = b4.w - m4.w * sc[3];
#pragma unroll
        for (int i = 0; i < 4; i++) {
            int mg = m0 + ty * 4 + i;
            int bb = mg >> 12;
            int hw = mg & 4095;
            float o[4];
#pragma unroll
            for (int j = 0; j < 4; j++) {
                float v = acc[i][j] * sc[j] + sb[j];
                v += xadd[(((size_t)(bb * DIM2 + nb + j)) << 12) + hw];
                o[j] = v;
            }
            *reinterpret_cast<float4*>(&C[(size_t)mg * N + nb]) =
                make_float4(o[0], o[1], o[2], o[3]);
        }
    } else {  // EPI == 2
        float4 bi = *reinterpret_cast<const float4*>(&bias[nb]);
#pragma unroll
        for (int i = 0; i < 4; i++) {
            int mg = m0 + ty * 4 + i;
            float4 old = *reinterpret_cast<const float4*>(&C[(size_t)mg * N + nb]);
            old.x += acc[i][0] + bi.x;
            old.y += acc[i][1] + bi.y;
            old.z += acc[i][2] + bi.z;
            old.w += acc[i][3] + bi.w;
            *reinterpret_cast<float4*>(&C[(size_t)mg * N + nb]) = old;
        }
    }
}

// ---------------------------------------------------------------------------
// Axial attention over one (b, x, head) slice: 64 q x 64 k, dh=32.
// Q row-major [NTOK, 256], KV row-major [NTOK, 512] (k cols 0..255, v 256..511)
// axis 0: attend over H (token step 64, base offset = w)
// axis 1: attend over W (token step 1,  base offset = h*64)
// accum:  0 -> O = result, 1 -> O += result
// ---------------------------------------------------------------------------
__global__ __launch_bounds__(64)
void axial_attn_kernel(const float* __restrict__ Q, const float* __restrict__ KV,
                       float* __restrict__ O, int axis, int accum) {
    __shared__ float ks[64][32];
    __shared__ float vs[64][32];
    __shared__ float ss[64][65];

    const int i = threadIdx.x;          // query row
    const int bx = blockIdx.x;
    const int b = bx >> 9;
    const int rem = bx & 511;
    const int x = rem >> 3;
    const int nh = rem & 7;
    const int base = b * 4096 + (axis ? x * 64 : x);
    const int step = axis ? 1 : 64;
    const int hoff = nh * DHEAD;

    // load k, v row i into smem
    {
        const float* kp = KV + (size_t)(base + i * step) * 512 + hoff;
#pragma unroll
        for (int d4 = 0; d4 < 8; d4++) {
            *reinterpret_cast<float4*>(&ks[i][d4 * 4]) =
                *reinterpret_cast<const float4*>(kp + d4 * 4);
            *reinterpret_cast<float4*>(&vs[i][d4 * 4]) =
                *reinterpret_cast<const float4*>(kp + 256 + d4 * 4);
        }
    }
    // load own q row into registers
    float qreg[32];
    {
        const float* qp = Q + (size_t)(base + i * step) * 256 + hoff;
#pragma unroll
        for (int d4 = 0; d4 < 8; d4++) {
            float4 t = *reinterpret_cast<const float4*>(qp + d4 * 4);
            qreg[d4 * 4 + 0] = t.x;
            qreg[d4 * 4 + 1] = t.y;
            qreg[d4 * 4 + 2] = t.z;
            qreg[d4 * 4 + 3] = t.w;
        }
    }
    __syncthreads();

    const float scale = 0.17677669529663687f;  // 1/sqrt(32)
    float mx = -1e30f;
#pragma unroll 2
    for (int j = 0; j < 64; j++) {
        float a = 0.f;
#pragma unroll
        for (int d4 = 0; d4 < 8; d4++) {
            float4 k4 = *reinterpret_cast<const float4*>(&ks[j][d4 * 4]);
            a += qreg[d4 * 4 + 0] * k4.x + qreg[d4 * 4 + 1] * k4.y +
                 qreg[d4 * 4 + 2] * k4.z + qreg[d4 * 4 + 3] * k4.w;
        }
        a *= scale;
        ss[i][j] = a;
        mx = fmaxf(mx, a);
    }
    float sum = 0.f;
#pragma unroll 2
    for (int j = 0; j < 64; j++) {
        float p = __expf(ss[i][j] - mx);
        ss[i][j] = p;
        sum += p;
    }
    float inv = 1.0f / sum;

    float o[32];
#pragma unroll
    for (int d = 0; d < 32; d++) o[d] = 0.f;
#pragma unroll 2
    for (int j = 0; j < 64; j++) {
        float p = ss[i][j];
#pragma unroll
        for (int d4 = 0; d4 < 8; d4++) {
            float4 v4 = *reinterpret_cast<const float4*>(&vs[j][d4 * 4]);
            o[d4 * 4 + 0] += p * v4.x;
            o[d4 * 4 + 1] += p * v4.y;
            o[d4 * 4 + 2] += p * v4.z;
            o[d4 * 4 + 3] += p * v4.w;
        }
    }

    float* op = O + (size_t)(base + i * step) * 256 + hoff;
    if (accum) {
#pragma unroll
        for (int d4 = 0; d4 < 8; d4++) {
            float4 t = *reinterpret_cast<const float4*>(op + d4 * 4);
            t.x += o[d4 * 4 + 0] * inv;
            t.y += o[d4 * 4 + 1] * inv;
            t.z += o[d4 * 4 + 2] * inv;
            t.w += o[d4 * 4 + 3] * inv;
            *reinterpret_cast<float4*>(op + d4 * 4) = t;
        }
    } else {
#pragma unroll
        for (int d4 = 0; d4 < 8; d4++) {
            float4 t = make_float4(o[d4 * 4 + 0] * inv, o[d4 * 4 + 1] * inv,
                                   o[d4 * 4 + 2] * inv, o[d4 * 4 + 3] * inv);
            *reinterpret_cast<float4*>(op + d4 * 4) = t;
        }
    }
}

// ---------------------------------------------------------------------------
// Final transpose: acc [token, 256] -> out [B, 256, H, W]
// ---------------------------------------------------------------------------
__global__ void transpose_out_kernel(const float* __restrict__ acc,
                                     float* __restrict__ out) {
    __shared__ float t[32][33];
    int b = blockIdx.z;
    int hw0 = blockIdx.x * 32;
    int c0 = blockIdx.y * 32;
    int tx = threadIdx.x, ty = threadIdx.y;  // 32 x 8
#pragma unroll
    for (int q = 0; q < 4; q++)
        t[ty + q * 8][tx] =
            acc[((size_t)b * 4096 + hw0 + ty + q * 8) * 256 + c0 + tx];
    __syncthreads();
#pragma unroll
    for (int q = 0; q < 4; q++)
        out[(((size_t)(b * 256 + c0 + ty + q * 8)) << 12) + hw0 + tx] =
            t[tx][ty + q * 8];
}

// ---------------------------------------------------------------------------
// Launch
// ---------------------------------------------------------------------------
extern "C" void kernel_launch(void* const* d_in, const int* in_sizes, int n_in,
                              void* d_out, int out_size) {
    const float* x1     = (const float*)d_in[0];
    const float* x2     = (const float*)d_in[1];
    const float* ln1q_w = (const float*)d_in[2];
    const float* ln1q_b = (const float*)d_in[3];
    const float* ln2kv_w= (const float*)d_in[4];
    const float* ln2kv_b= (const float*)d_in[5];
    const float* Wq1    = (const float*)d_in[6];
    const float* Wkv2   = (const float*)d_in[7];
    const float* Wout1  = (const float*)d_in[8];
    const float* bout1  = (const float*)d_in[9];
    const float* ln2q_w = (const float*)d_in[10];
    const float* ln2q_b = (const float*)d_in[11];
    const float* ln1kv_w= (const float*)d_in[12];
    const float* ln1kv_b= (const float*)d_in[13];
    const float* Wq2    = (const float*)d_in[14];
    const float* Wkv1   = (const float*)d_in[15];
    const float* Wout2  = (const float*)d_in[16];
    const float* bout2  = (const float*)d_in[17];
    const float* Wsc    = (const float*)d_in[18];
    const float* bng    = (const float*)d_in[19];
    const float* bnb    = (const float*)d_in[20];
    const float* bnm    = (const float*)d_in[21];
    const float* bnv    = (const float*)d_in[22];
    float* out = (float*)d_out;

    float* S = nullptr;
    cudaGetSymbolAddress((void**)&S, g_scratch);
    float* mu1  = S + OFF_MU1;
    float* rs1  = S + OFF_RS1;
    float* mu2  = S + OFF_MU2;
    float* rs2  = S + OFF_RS2;
    float* WscT = S + OFF_WSCT;
    float* q1   = S + OFF_Q1;
    float* q2   = S + OFF_Q2;
    float* kv1  = S + OFF_KV1;
    float* kv2  = S + OFF_KV2;
    float* o1   = S + OFF_O1;
    float* o2   = S + OFF_O2;
    float* accb = S + OFF_ACC;

    // 1) LN stats + Wsc transpose
    ln_stats_kernel<<<NTOK / 256, 256>>>(x1, DIM1, mu1, rs1);
    ln_stats_kernel<<<NTOK / 256, 256>>>(x2, DIM2, mu2, rs2);
    transpose_wsc_kernel<<<dim3(12, 8), dim3(32, 8)>>>(Wsc, WscT);

    // 2) Input projections (LN fused into A-operand)
    gemm_kernel<0, 1, 0><<<dim3(NTOK / 64, 4), 256>>>(
        x1, Wq1, q1, 256, DIM1, mu1, rs1, ln1q_w, ln1q_b,
        nullptr, nullptr, nullptr, nullptr, nullptr, nullptr);
    gemm_kernel<0, 1, 0><<<dim3(NTOK / 64, 8), 256>>>(
        x2, Wkv2, kv2, 512, DIM2, mu2, rs2, ln2kv_w, ln2kv_b,
        nullptr, nullptr, nullptr, nullptr, nullptr, nullptr);
    gemm_kernel<0, 1, 0><<<dim3(NTOK / 64, 4), 256>>>(
        x2, Wq2, q2, 256, DIM2, mu2, rs2, ln2q_w, ln2q_b,
        nullptr, nullptr, nullptr, nullptr, nullptr, nullptr);
    gemm_kernel<0, 1, 0><<<dim3(NTOK / 64, 8), 256>>>(
        x1, Wkv1, kv1, 512, DIM1, mu1, rs1, ln1kv_w, ln1kv_b,
        nullptr, nullptr, nullptr, nullptr, nullptr, nullptr);

    // 3) Shortcut 1x1 conv + BN + x2 residual -> accumulator
    gemm_kernel<0, 0, 1><<<dim3(NTOK / 64, 4), 256>>>(
        x1, WscT, accb, 256, DIM1, nullptr, nullptr, nullptr, nullptr,
        nullptr, bng, bnb, bnm, bnv, x2);

    // 4) Axial attention (row pass writes, col pass accumulates)
    axial_attn_kernel<<<4096, 64>>>(q1, kv2, o1, 0, 0);
    axial_attn_kernel<<<4096, 64>>>(q1, kv2, o1, 1, 1);
    axial_attn_kernel<<<4096, 64>>>(q2, kv1, o2, 0, 0);
    axial_attn_kernel<<<4096, 64>>>(q2, kv1, o2, 1, 1);

    // 5) Output projections accumulated into the accumulator
    gemm_kernel<1, 0, 2><<<dim3(NTOK / 64, 4), 256>>>(
        o1, Wout1, accb, 256, INNER, nullptr, nullptr, nullptr, nullptr,
        bout1, nullptr, nullptr, nullptr, nullptr, nullptr);
    gemm_kernel<1, 0, 2><<<dim3(NTOK / 64, 4), 256>>>(
        o2, Wout2, accb, 256, INNER, nullptr, nullptr, nullptr, nullptr,
        bout2, nullptr, nullptr, nullptr, nullptr, nullptr);

    // 6) NHWC -> NCHW
    transpose_out_kernel<<<dim3(128, 8, 8), dim3(32, 8)>>>(accb, out);
}

// round 12
// speedup vs baseline: 1.5210x; 1.5210x over previous
#include <cuda_runtime.h>
#include <cstdint>
#include <cstddef>

// ---------------------------------------------------------------------------
// Problem constants
// ---------------------------------------------------------------------------
#define BATCH 8
#define DIM1 384
#define DIM2 256
#define DHEAD 32
#define NTOK 32768
#define LN_EPS 1e-5f

// ---------------------------------------------------------------------------
// Helpers (baseline PTX only — no sm_103a-suffixed features!)
// ---------------------------------------------------------------------------
__device__ __forceinline__ uint32_t smem_u32(const void* p) {
    uint32_t a;
    asm("{ .reg .u64 t; cvta.to.shared.u64 t, %1; cvt.u32.u64 %0, t; }"
        : "=r"(a) : "l"(p));
    return a;
}
__device__ __forceinline__ float tf32r(float x) {
    uint32_t u;
    asm("cvt.rna.tf32.f32 %0, %1;" : "=r"(u) : "f"(x));
    return __uint_as_float(u);
}
__device__ __forceinline__ void cp16(uint32_t s, const void* g) {
    asm volatile("cp.async.cg.shared.global [%0], [%1], 16;" :: "r"(s), "l"(g));
}
__device__ __forceinline__ void mma_tf32(float* c, const uint32_t* a,
                                         const uint32_t* b) {
    asm volatile(
        "mma.sync.aligned.m16n8k8.row.col.f32.tf32.tf32.f32 "
        "{%0,%1,%2,%3}, {%4,%5,%6,%7}, {%8,%9}, {%0,%1,%2,%3};"
        : "+f"(c[0]), "+f"(c[1]), "+f"(c[2]), "+f"(c[3])
        : "r"(a[0]), "r"(a[1]), "r"(a[2]), "r"(a[3]), "r"(b[0]), "r"(b[1]));
}

// ---------------------------------------------------------------------------
// Scratch
// ---------------------------------------------------------------------------
constexpr size_t OFF_MU1  = 0;
constexpr size_t OFF_RS1  = OFF_MU1 + NTOK;
constexpr size_t OFF_MU2  = OFF_RS1 + NTOK;
constexpr size_t OFF_RS2  = OFF_MU2 + NTOK;
constexpr size_t OFF_A1N  = OFF_RS2 + NTOK;                    // 32768*384
constexpr size_t OFF_A2N  = OFF_A1N + (size_t)NTOK * DIM1;     // 32768*256
constexpr size_t OFF_B1   = OFF_A2N + (size_t)NTOK * DIM2;     // 768*384
constexpr size_t OFF_B2   = OFF_B1 + 768 * 384;                // 768*256
constexpr size_t OFF_BSC  = OFF_B2 + 768 * 256;                // 256*384
constexpr size_t OFF_BO1  = OFF_BSC + 256 * 384;               // 256*256
constexpr size_t OFF_BO2  = OFF_BO1 + 256 * 256;               // 256*256
constexpr size_t OFF_VB1  = OFF_BO2 + 256 * 256;               // 768
constexpr size_t OFF_VB2  = OFF_VB1 + 768;                     // 768
constexpr size_t OFF_VBSC = OFF_VB2 + 768;                     // 256
constexpr size_t OFF_WSUM = OFF_VBSC + 256;                    // 256
constexpr size_t OFF_P1   = OFF_WSUM + 256;                    // 32768*768
constexpr size_t OFF_P2   = OFF_P1 + (size_t)NTOK * 768;       // 32768*768
constexpr size_t OFF_O1   = OFF_P2 + (size_t)NTOK * 768;       // 32768*256
constexpr size_t OFF_O2   = OFF_O1 + (size_t)NTOK * 256;
constexpr size_t OFF_ACC  = OFF_O2 + (size_t)NTOK * 256;
constexpr size_t SCRATCH_TOTAL = OFF_ACC + (size_t)NTOK * 256;

__device__ __align__(128) float g_scratch[SCRATCH_TOTAL];

// ---------------------------------------------------------------------------
// LN stats per token
// ---------------------------------------------------------------------------
__global__ void ln_stats_kernel(const float* __restrict__ x, int C,
                                float* __restrict__ mu, float* __restrict__ rs) {
    int m = blockIdx.x * blockDim.x + threadIdx.x;
    int b = m >> 12;
    int hw = m & 4095;
    const float* p = x + ((size_t)b * C << 12) + hw;
    float s = 0.f, s2 = 0.f;
    for (int c = 0; c < C; c++) {
        float v = p[(size_t)c << 12];
        s += v;
        s2 += v * v;
    }
    float invC = 1.0f / (float)C;
    float mean = s * invC;
    float var = s2 * invC - mean * mean;
    mu[m] = mean;
    rs[m] = rsqrtf(var + LN_EPS);
}

// ---------------------------------------------------------------------------
// NCHW -> row-major normalized [NTOK, C]:  (x-mu)*rs, tf32-rounded
// ---------------------------------------------------------------------------
__global__ void prep_a_kernel(const float* __restrict__ x, int C,
                              const float* __restrict__ mu,
                              const float* __restrict__ rs,
                              float* __restrict__ Arow) {
    __shared__ float t[32][33];
    int b = blockIdx.z;
    int hw0 = blockIdx.x * 32;
    int c0 = blockIdx.y * 32;
    int tx = threadIdx.x, ty = threadIdx.y;  // 32 x 8
#pragma unroll
    for (int q = 0; q < 4; q++)
        t[ty + q * 8][tx] = x[(((size_t)(b * C + c0 + ty + q * 8)) << 12) + hw0 + tx];
    __syncthreads();
#pragma unroll
    for (int q = 0; q < 4; q++) {
        int m = b * 4096 + hw0 + ty + q * 8;
        float v = (t[tx][ty + q * 8] - mu[m]) * rs[m];
        Arow[(size_t)m * C + c0 + tx] = tf32r(v);
    }
}

// ---------------------------------------------------------------------------
// Weight prep: W [K,N] row-major -> Bt [N,K] K-major, scaled by lnw[k], tf32
// ---------------------------------------------------------------------------
__global__ void prep_w_kernel(const float* __restrict__ W, int K, int N,
                              const float* __restrict__ lnw,
                              float* __restrict__ Bt) {
    __shared__ float t[32][33];
    int k0 = blockIdx.x * 32;
    int n0 = blockIdx.y * 32;
    int tx = threadIdx.x, ty = threadIdx.y;
#pragma unroll
    for (int q = 0; q < 4; q++)
        t[ty + q * 8][tx] = W[(size_t)(k0 + ty + q * 8) * N + n0 + tx];
    __syncthreads();
#pragma unroll
    for (int q = 0; q < 4; q++) {
        int k = k0 + tx;
        float s = lnw ? lnw[k] : 1.0f;
        Bt[(size_t)(n0 + ty + q * 8) * K + k] = tf32r(t[tx][ty + q * 8] * s);
    }
}

// Wsc is [N=256, K=384] already; scale each row by BN scale, tf32 round.
__global__ void prep_wsc_kernel(const float* __restrict__ Wsc,
                                const float* __restrict__ g,
                                const float* __restrict__ v,
                                float* __restrict__ Bt) {
    int idx = blockIdx.x * blockDim.x + threadIdx.x;
    if (idx >= 256 * 384) return;
    int n = idx / 384;
    float s = rsqrtf(v[n] + LN_EPS) * g[n];
    Bt[idx] = tf32r(Wsc[idx] * s);
}

// bias vector: addb[n] = sum_k lnb[k]*W[k,n]
__global__ void prep_bias_kernel(const float* __restrict__ W, int K, int N,
                                 const float* __restrict__ lnb,
                                 float* __restrict__ addb) {
    int n = blockIdx.x * blockDim.x + threadIdx.x;
    if (n >= N) return;
    float s = 0.f;
    for (int k = 0; k < K; k++) s += lnb[k] * W[(size_t)k * N + n];
    addb[n] = s;
}

// shortcut: addb[n] = bnb - bnm*s ;  wsum[n] = s * sum_k Wsc[n,k]
__global__ void prep_sc_bias_kernel(const float* __restrict__ Wsc,
                                    const float* __restrict__ g,
                                    const float* __restrict__ bta,
                                    const float* __restrict__ mn,
                                    const float* __restrict__ vr,
                                    float* __restrict__ addb,
                                    float* __restrict__ wsum) {
    int n = threadIdx.x;
    if (n >= 256) return;
    float s = rsqrtf(vr[n] + LN_EPS) * g[n];
    addb[n] = bta[n] - mn[n] * s;
    float ws = 0.f;
    for (int k = 0; k < 384; k++) ws += Wsc[(size_t)n * 384 + k];
    wsum[n] = ws * s;
}

// ---------------------------------------------------------------------------
// mma.sync tf32 GEMM: C[M,NC] tile(128x128) = A[M,K] @ Bt[NC,K]^T
// 8 warps, warp tile 32(m) x 64(n), m16n8k8 tf32, KC=16, 2-stage cp.async.
// EPI 0: C = D + addb[n]
// EPI 1: C = D*(1/rs[m]) + mu[m]*wsum[n] + addb[n] + xg[(b,n,hw)]   (shortcut)
// EPI 2: C += D + addb[n]
// ---------------------------------------------------------------------------
#define SAS 20     // smem row stride (floats) for 16-float rows + pad

template <int EPI>
__global__ __launch_bounds__(256, 2)
void mma_gemm(const float* __restrict__ A, const float* __restrict__ Bt,
              float* __restrict__ C, int K, int NC,
              const float* __restrict__ addb,
              const float* __restrict__ mu, const float* __restrict__ rs,
              const float* __restrict__ wsum, const float* __restrict__ xg) {
    __shared__ __align__(16) float sAB[2][2][128 * SAS];

    const int tid = threadIdx.x;
    const int warp = tid >> 5, lane = tid & 31;
    const int wm = warp >> 1, wn = warp & 1;
    const int g = lane >> 2, t4 = lane & 3;
    const int n0 = blockIdx.x * 128;
    const int m0 = blockIdx.y * 128;

    const float* Abase = A + (size_t)m0 * K;
    const float* Bbase = Bt + (size_t)n0 * K;

    // per-thread global-load mapping: 2 float4 per tile per chunk
    const int lr = tid >> 2;              // row 0..63 (+64 on second iter)
    const int lq = (tid & 3) << 2;        // k offset 0,4,8,12

    uint32_t sAaddr[2], sBaddr[2];
    sAaddr[0] = smem_u32(&sAB[0][0][0]);
    sAaddr[1] = smem_u32(&sAB[1][0][0]);
    sBaddr[0] = smem_u32(&sAB[0][1][0]);
    sBaddr[1] = smem_u32(&sAB[1][1][0]);

    float acc[2][8][4];
#pragma unroll
    for (int mt = 0; mt < 2; mt++)
#pragma unroll
        for (int nt = 0; nt < 8; nt++)
#pragma unroll
            for (int u = 0; u < 4; u++) acc[mt][nt][u] = 0.f;

    const int nch = K >> 4;

    // prologue: load chunk 0 into stage 0
#pragma unroll
    for (int i = 0; i < 2; i++) {
        int r = lr + (i << 6);
        cp16(sAaddr[0] + (uint32_t)(r * SAS + lq) * 4, Abase + (size_t)r * K + lq);
        cp16(sBaddr[0] + (uint32_t)(r * SAS + lq) * 4, Bbase + (size_t)r * K + lq);
    }
    asm volatile("cp.async.commit_group;" ::: "memory");

    for (int ch = 0; ch < nch; ch++) {
        const int st = ch & 1;
        if (ch + 1 < nch) {
            const int k0 = (ch + 1) << 4;
            const int st2 = st ^ 1;
#pragma unroll
            for (int i = 0; i < 2; i++) {
                int r = lr + (i << 6);
                cp16(sAaddr[st2] + (uint32_t)(r * SAS + lq) * 4,
                     Abase + (size_t)r * K + k0 + lq);
                cp16(sBaddr[st2] + (uint32_t)(r * SAS + lq) * 4,
                     Bbase + (size_t)r * K + k0 + lq);
            }
            asm volatile("cp.async.commit_group;" ::: "memory");
            asm volatile("cp.async.wait_group 1;" ::: "memory");
        } else {
            asm volatile("cp.async.wait_group 0;" ::: "memory");
        }
        __syncthreads();

        const float* a_s = sAB[st][0];
        const float* b_s = sAB[st][1];
#pragma unroll
        for (int kk = 0; kk < 2; kk++) {
            const int kb = (kk << 3) + t4;
            uint32_t af[2][4];
#pragma unroll
            for (int mt = 0; mt < 2; mt++) {
                int m = wm * 32 + mt * 16 + g;
                af[mt][0] = __float_as_uint(a_s[m * SAS + kb]);
                af[mt][1] = __float_as_uint(a_s[(m + 8) * SAS + kb]);
                af[mt][2] = __float_as_uint(a_s[m * SAS + kb + 4]);
                af[mt][3] = __float_as_uint(a_s[(m + 8) * SAS + kb + 4]);
            }
            uint32_t bf[8][2];
#pragma unroll
            for (int nt = 0; nt < 8; nt++) {
                int n = wn * 64 + nt * 8 + g;
                bf[nt][0] = __float_as_uint(b_s[n * SAS + kb]);
                bf[nt][1] = __float_as_uint(b_s[n * SAS + kb + 4]);
            }
#pragma unroll
            for (int mt = 0; mt < 2; mt++)
#pragma unroll
                for (int nt = 0; nt < 8; nt++)
                    mma_tf32(acc[mt][nt], af[mt], bf[nt]);
        }
        __syncthreads();
    }

    // ---- epilogue ----
    const int r0base = m0 + wm * 32 + g;
    const int cbase = n0 + wn * 64 + 2 * t4;

    if (EPI == 0) {
#pragma unroll
        for (int mt = 0; mt < 2; mt++) {
            int r0 = r0base + mt * 16;
#pragma unroll
            for (int nt = 0; nt < 8; nt++) {
                int cn = cbase + nt * 8;
                float b0 = addb[cn], b1 = addb[cn + 1];
                float2 v0 = make_float2(acc[mt][nt][0] + b0, acc[mt][nt][1] + b1);
                float2 v1 = make_float2(acc[mt][nt][2] + b0, acc[mt][nt][3] + b1);
                *reinterpret_cast<float2*>(&C[(size_t)r0 * NC + cn]) = v0;
                *reinterpret_cast<float2*>(&C[(size_t)(r0 + 8) * NC + cn]) = v1;
            }
        }
    } else if (EPI == 1) {
#pragma unroll
        for (int mt = 0; mt < 2; mt++) {
            int r0 = r0base + mt * 16;
            int r1 = r0 + 8;
            float i0 = 1.0f / rs[r0], m0v = mu[r0];
            float i1 = 1.0f / rs[r1], m1v = mu[r1];
            int b0i = r0 >> 12, hw0 = r0 & 4095;
            int b1i = r1 >> 12, hw1 = r1 & 4095;
#pragma unroll
            for (int nt = 0; nt < 8; nt++) {
                int cn = cbase + nt * 8;
                float a0 = addb[cn], a1 = addb[cn + 1];
                float w0 = wsum[cn], w1 = wsum[cn + 1];
                float2 v0, v1;
                v0.x = acc[mt][nt][0] * i0 + m0v * w0 + a0 +
                       xg[(((size_t)((b0i << 8) + cn)) << 12) + hw0];
                v0.y = acc[mt][nt][1] * i0 + m0v * w1 + a1 +
                       xg[(((size_t)((b0i << 8) + cn + 1)) << 12) + hw0];
                v1.x = acc[mt][nt][2] * i1 + m1v * w0 + a0 +
                       xg[(((size_t)((b1i << 8) + cn)) << 12) + hw1];
                v1.y = acc[mt][nt][3] * i1 + m1v * w1 + a1 +
                       xg[(((size_t)((b1i << 8) + cn + 1)) << 12) + hw1];
                *reinterpret_cast<float2*>(&C[(size_t)r0 * NC + cn]) = v0;
                *reinterpret_cast<float2*>(&C[(size_t)r1 * NC + cn]) = v1;
            }
        }
    } else {  // EPI == 2
#pragma unroll
        for (int mt = 0; mt < 2; mt++) {
            int r0 = r0base + mt * 16;
#pragma unroll
            for (int nt = 0; nt < 8; nt++) {
                int cn = cbase + nt * 8;
                float b0 = addb[cn], b1 = addb[cn + 1];
                float2 o0 = *reinterpret_cast<const float2*>(&C[(size_t)r0 * NC + cn]);
                float2 o1 = *reinterpret_cast<const float2*>(&C[(size_t)(r0 + 8) * NC + cn]);
                o0.x += acc[mt][nt][0] + b0;
                o0.y += acc[mt][nt][1] + b1;
                o1.x += acc[mt][nt][2] + b0;
                o1.y += acc[mt][nt][3] + b1;
                *reinterpret_cast<float2*>(&C[(size_t)r0 * NC + cn]) = o0;
                *reinterpret_cast<float2*>(&C[(size_t)(r0 + 8) * NC + cn]) = o1;
            }
        }
    }
}

// ---------------------------------------------------------------------------
// Axial attention over one (b, x, head) slice: 64 q x 64 k, dh=32.
// Q rows stride qstr (cols 0..255 are the q heads), KV rows stride kvstr
// (k at +0, v at +256 within the passed base pointer).
// ---------------------------------------------------------------------------
__global__ __launch_bounds__(64)
void axial_attn_kernel(const float* __restrict__ Q, int qstr,
                       const float* __restrict__ KV, int kvstr,
                       float* __restrict__ O, int axis, int accum) {
    __shared__ float ks[64][32];
    __shared__ float vs[64][32];
    __shared__ float ss[64][65];

    const int i = threadIdx.x;
    const int bx = blockIdx.x;
    const int b = bx >> 9;
    const int rem = bx & 511;
    const int x = rem >> 3;
    const int nh = rem & 7;
    const int base = b * 4096 + (axis ? x * 64 : x);
    const int step = axis ? 1 : 64;
    const int hoff = nh * DHEAD;

    {
        const float* kp = KV + (size_t)(base + i * step) * kvstr + hoff;
#pragma unroll
        for (int d4 = 0; d4 < 8; d4++) {
            *reinterpret_cast<float4*>(&ks[i][d4 * 4]) =
                *reinterpret_cast<const float4*>(kp + d4 * 4);
            *reinterpret_cast<float4*>(&vs[i][d4 * 4]) =
                *reinterpret_cast<const float4*>(kp + 256 + d4 * 4);
        }
    }
    float qreg[32];
    {
        const float* qp = Q + (size_t)(base + i * step) * qstr + hoff;
#pragma unroll
        for (int d4 = 0; d4 < 8; d4++) {
            float4 t = *reinterpret_cast<const float4*>(qp + d4 * 4);
            qreg[d4 * 4 + 0] = t.x; qreg[d4 * 4 + 1] = t.y;
            qreg[d4 * 4 + 2] = t.z; qreg[d4 * 4 + 3] = t.w;
        }
    }
    __syncthreads();

    const float scale = 0.17677669529663687f;
    float mx = -1e30f;
#pragma unroll 2
    for (int j = 0; j < 64; j++) {
        float a = 0.f;
#pragma unroll
        for (int d4 = 0; d4 < 8; d4++) {
            float4 k4 = *reinterpret_cast<const float4*>(&ks[j][d4 * 4]);
            a += qreg[d4 * 4 + 0] * k4.x + qreg[d4 * 4 + 1] * k4.y +
                 qreg[d4 * 4 + 2] * k4.z + qreg[d4 * 4 + 3] * k4.w;
        }
        a *= scale;
        ss[i][j] = a;
        mx = fmaxf(mx, a);
    }
    float sum = 0.f;
#pragma unroll 2
    for (int j = 0; j < 64; j++) {
        float p = __expf(ss[i][j] - mx);
        ss[i][j] = p;
        sum += p;
    }
    float inv = 1.0f / sum;

    float o[32];
#pragma unroll
    for (int d = 0; d < 32; d++) o[d] = 0.f;
#pragma unroll 2
    for (int j = 0; j < 64; j++) {
        float p = ss[i][j];
#pragma unroll
        for (int d4 = 0; d4 < 8; d4++) {
            float4 v4 = *reinterpret_cast<const float4*>(&vs[j][d4 * 4]);
            o[d4 * 4 + 0] += p * v4.x; o[d4 * 4 + 1] += p * v4.y;
            o[d4 * 4 + 2] += p * v4.z; o[d4 * 4 + 3] += p * v4.w;
        }
    }

    float* op = O + (size_t)(base + i * step) * 256 + hoff;
    if (accum) {
#pragma unroll
        for (int d4 = 0; d4 < 8; d4++) {
            float4 t = *reinterpret_cast<const float4*>(op + d4 * 4);
            t.x += o[d4 * 4 + 0] * inv; t.y += o[d4 * 4 + 1] * inv;
            t.z += o[d4 * 4 + 2] * inv; t.w += o[d4 * 4 + 3] * inv;
            *reinterpret_cast<float4*>(op + d4 * 4) = t;
        }
    } else {
#pragma unroll
        for (int d4 = 0; d4 < 8; d4++) {
            float4 t = make_float4(o[d4 * 4 + 0] * inv, o[d4 * 4 + 1] * inv,
                                   o[d4 * 4 + 2] * inv, o[d4 * 4 + 3] * inv);
            *reinterpret_cast<float4*>(op + d4 * 4) = t;
        }
    }
}

// ---------------------------------------------------------------------------
// Final transpose: acc [token, 256] -> out [B, 256, H, W]
// ---------------------------------------------------------------------------
__global__ void transpose_out_kernel(const float* __restrict__ acc,
                                     float* __restrict__ out) {
    __shared__ float t[32][33];
    int b = blockIdx.z;
    int hw0 = blockIdx.x * 32;
    int c0 = blockIdx.y * 32;
    int tx = threadIdx.x, ty = threadIdx.y;
#pragma unroll
    for (int q = 0; q < 4; q++)
        t[ty + q * 8][tx] =
            acc[((size_t)b * 4096 + hw0 + ty + q * 8) * 256 + c0 + tx];
    __syncthreads();
#pragma unroll
    for (int q = 0; q < 4; q++)
        out[(((size_t)(b * 256 + c0 + ty + q * 8)) << 12) + hw0 + tx] =
            t[tx][ty + q * 8];
}

// ---------------------------------------------------------------------------
// Launch
// ---------------------------------------------------------------------------
extern "C" void kernel_launch(void* const* d_in, const int* in_sizes, int n_in,
                              void* d_out, int out_size) {
    const float* x1     = (const float*)d_in[0];
    const float* x2     = (const float*)d_in[1];
    const float* ln1q_w = (const float*)d_in[2];
    const float* ln1q_b = (const float*)d_in[3];
    const float* ln2kv_w= (const float*)d_in[4];
    const float* ln2kv_b= (const float*)d_in[5];
    const float* Wq1    = (const float*)d_in[6];
    const float* Wkv2   = (const float*)d_in[7];
    const float* Wout1  = (const float*)d_in[8];
    const float* bout1  = (const float*)d_in[9];
    const float* ln2q_w = (const float*)d_in[10];
    const float* ln2q_b = (const float*)d_in[11];
    const float* ln1kv_w= (const float*)d_in[12];
    const float* ln1kv_b= (const float*)d_in[13];
    const float* Wq2    = (const float*)d_in[14];
    const float* Wkv1   = (const float*)d_in[15];
    const float* Wout2  = (const float*)d_in[16];
    const float* bout2  = (const float*)d_in[17];
    const float* Wsc    = (const float*)d_in[18];
    const float* bng    = (const float*)d_in[19];
    const float* bnb    = (const float*)d_in[20];
    const float* bnm    = (const float*)d_in[21];
    const float* bnv    = (const float*)d_in[22];
    float* out = (float*)d_out;

    float* S = nullptr;
    cudaGetSymbolAddress((void**)&S, g_scratch);
    float* mu1  = S + OFF_MU1;  float* rs1 = S + OFF_RS1;
    float* mu2  = S + OFF_MU2;  float* rs2 = S + OFF_RS2;
    float* A1n  = S + OFF_A1N;  float* A2n = S + OFF_A2N;
    float* B1   = S + OFF_B1;   float* B2  = S + OFF_B2;
    float* Bsc  = S + OFF_BSC;  float* Bo1 = S + OFF_BO1;  float* Bo2 = S + OFF_BO2;
    float* vb1  = S + OFF_VB1;  float* vb2 = S + OFF_VB2;
    float* vbsc = S + OFF_VBSC; float* wsum= S + OFF_WSUM;
    float* P1   = S + OFF_P1;   float* P2  = S + OFF_P2;
    float* o1   = S + OFF_O1;   float* o2  = S + OFF_O2;
    float* accb = S + OFF_ACC;

    dim3 tb(32, 8);

    // 1) stats + A preps
    ln_stats_kernel<<<NTOK / 256, 256>>>(x1, DIM1, mu1, rs1);
    ln_stats_kernel<<<NTOK / 256, 256>>>(x2, DIM2, mu2, rs2);
    prep_a_kernel<<<dim3(128, 12, 8), tb>>>(x1, DIM1, mu1, rs1, A1n);
    prep_a_kernel<<<dim3(128, 8, 8), tb>>>(x2, DIM2, mu2, rs2, A2n);

    // 2) weight preps: B1 = [q1 | kv1] (K=384), B2 = [q2 | kv2] (K=256)
    prep_w_kernel<<<dim3(12, 8), tb>>>(Wq1, 384, 256, ln1q_w, B1);
    prep_w_kernel<<<dim3(12, 16), tb>>>(Wkv1, 384, 512, ln1kv_w, B1 + 256 * 384);
    prep_w_kernel<<<dim3(8, 8), tb>>>(Wq2, 256, 256, ln2q_w, B2);
    prep_w_kernel<<<dim3(8, 16), tb>>>(Wkv2, 256, 512, ln2kv_w, B2 + 256 * 256);
    prep_w_kernel<<<dim3(8, 8), tb>>>(Wout1, 256, 256, nullptr, Bo1);
    prep_w_kernel<<<dim3(8, 8), tb>>>(Wout2, 256, 256, nullptr, Bo2);
    prep_wsc_kernel<<<384, 256>>>(Wsc, bng, bnv, Bsc);
    prep_bias_kernel<<<1, 256>>>(Wq1, 384, 256, ln1q_b, vb1);
    prep_bias_kernel<<<2, 256>>>(Wkv1, 384, 512, ln1kv_b, vb1 + 256);
    prep_bias_kernel<<<1, 256>>>(Wq2, 256, 256, ln2q_b, vb2);
    prep_bias_kernel<<<2, 256>>>(Wkv2, 256, 512, ln2kv_b, vb2 + 256);
    prep_sc_bias_kernel<<<1, 256>>>(Wsc, bng, bnb, bnm, bnv, vbsc, wsum);

    // 3) fused projections:  P1 = A1n @ B1^T (q1|k1|v1),  P2 = A2n @ B2^T
    mma_gemm<0><<<dim3(6, 256), 256>>>(A1n, B1, P1, 384, 768, vb1,
                                       nullptr, nullptr, nullptr, nullptr);
    mma_gemm<0><<<dim3(6, 256), 256>>>(A2n, B2, P2, 256, 768, vb2,
                                       nullptr, nullptr, nullptr, nullptr);

    // 4) shortcut GEMM -> acc = BN(x1f@Wsc^T) + x2f
    mma_gemm<1><<<dim3(2, 256), 256>>>(A1n, Bsc, accb, 384, 256, vbsc,
                                       mu1, rs1, wsum, x2);

    // 5) axial attention  (branch1: q=P1[:,0:256], kv=P2[:,256:768];
    //                      branch2: q=P2[:,0:256], kv=P1[:,256:768])
    axial_attn_kernel<<<4096, 64>>>(P1, 768, P2 + 256, 768, o1, 0, 0);
    axial_attn_kernel<<<4096, 64>>>(P1, 768, P2 + 256, 768, o1, 1, 1);
    axial_attn_kernel<<<4096, 64>>>(P2, 768, P1 + 256, 768, o2, 0, 0);
    axial_attn_kernel<<<4096, 64>>>(P2, 768, P1 + 256, 768, o2, 1, 1);

    // 6) output projections accumulate into acc
    mma_gemm<2><<<dim3(2, 256), 256>>>(o1, Bo1, accb, 256, 256, bout1,
                                       nullptr, nullptr, nullptr, nullptr);
    mma_gemm<2><<<dim3(2, 256), 256>>>(o2, Bo2, accb, 256, 256, bout2,
                                       nullptr, nullptr, nullptr, nullptr);

    // 7) NHWC -> NCHW
    transpose_out_kernel<<<dim3(128, 8, 8), tb>>>(accb, out);
}

// round 15
// speedup vs baseline: 2.4165x; 1.5887x over previous
#include <cuda_runtime.h>
#include <cuda_fp16.h>
#include <cstdint>
#include <cstddef>

// ---------------------------------------------------------------------------
// Problem constants
// ---------------------------------------------------------------------------
#define BATCH 8
#define DIM1 384
#define DIM2 256
#define NTOK 32768
#define LN_EPS 1e-5f

// ---------------------------------------------------------------------------
// Helpers (baseline PTX only: mma.sync fp16, ldmatrix, cp.async — no tcgen05)
// ---------------------------------------------------------------------------
__device__ __forceinline__ uint32_t smem_u32(const void* p) {
    uint32_t a;
    asm("{ .reg .u64 t; cvta.to.shared.u64 t, %1; cvt.u32.u64 %0, t; }"
        : "=r"(a) : "l"(p));
    return a;
}
__device__ __forceinline__ void cp16(uint32_t s, const void* g) {
    asm volatile("cp.async.cg.shared.global [%0], [%1], 16;" :: "r"(s), "l"(g));
}
__device__ __forceinline__ void mma_f16(float* c, const uint32_t* a,
                                        uint32_t b0, uint32_t b1) {
    asm volatile(
        "mma.sync.aligned.m16n8k16.row.col.f32.f16.f16.f32 "
        "{%0,%1,%2,%3}, {%4,%5,%6,%7}, {%8,%9}, {%0,%1,%2,%3};"
        : "+f"(c[0]), "+f"(c[1]), "+f"(c[2]), "+f"(c[3])
        : "r"(a[0]), "r"(a[1]), "r"(a[2]), "r"(a[3]), "r"(b0), "r"(b1));
}
__device__ __forceinline__ float fexp2(float x) {
    float r;
    asm("ex2.approx.f32 %0, %1;" : "=f"(r) : "f"(x));
    return r;
}

// ---------------------------------------------------------------------------
// Scratch layout (units: floats; half regions use 2 halfs per float slot)
// ---------------------------------------------------------------------------
constexpr size_t OFF_MU1  = 0;
constexpr size_t OFF_RS1  = OFF_MU1 + NTOK;
constexpr size_t OFF_MU2  = OFF_RS1 + NTOK;
constexpr size_t OFF_RS2  = OFF_MU2 + NTOK;
constexpr size_t OFF_A1H  = OFF_RS2 + NTOK;                     // 32768*384 h
constexpr size_t OFF_A2H  = OFF_A1H + (size_t)NTOK * DIM1 / 2;  // 32768*256 h
constexpr size_t OFF_B1H  = OFF_A2H + (size_t)NTOK * DIM2 / 2;  // 768*384 h
constexpr size_t OFF_B2H  = OFF_B1H + 768 * 384 / 2;            // 768*256 h
constexpr size_t OFF_BSCH = OFF_B2H + 768 * 256 / 2;            // 256*384 h
constexpr size_t OFF_BOCH = OFF_BSCH + 256 * 384 / 2;           // 256*512 h
constexpr size_t OFF_VB1  = OFF_BOCH + 256 * 512 / 2;           // 768 f
constexpr size_t OFF_VB2  = OFF_VB1 + 768;                      // 768 f
constexpr size_t OFF_VBOC = OFF_VB2 + 768;                      // 256 f
constexpr size_t OFF_VBSC = OFF_VBOC + 256;                     // 256 f
constexpr size_t OFF_WSUM = OFF_VBSC + 256;                     // 256 f
constexpr size_t OFF_P1   = OFF_WSUM + 256;                     // 32768*768 h
constexpr size_t OFF_P2   = OFF_P1 + (size_t)NTOK * 768 / 2;
constexpr size_t OFF_OH   = OFF_P2 + (size_t)NTOK * 768 / 2;    // 32768*512 h
constexpr size_t OFF_ACC  = OFF_OH + (size_t)NTOK * 512 / 2;    // 32768*256 f
constexpr size_t SCRATCH_TOTAL = OFF_ACC + (size_t)NTOK * 256;

__device__ __align__(128) float g_scratch[SCRATCH_TOTAL];

// ---------------------------------------------------------------------------
// LN stats per token
// ---------------------------------------------------------------------------
__global__ void ln_stats_kernel(const float* __restrict__ x, int C,
                                float* __restrict__ mu, float* __restrict__ rs) {
    int m = blockIdx.x * blockDim.x + threadIdx.x;
    int b = m >> 12;
    int hw = m & 4095;
    const float* p = x + ((size_t)b * C << 12) + hw;
    float s = 0.f, s2 = 0.f;
    for (int c = 0; c < C; c++) {
        float v = p[(size_t)c << 12];
        s += v;
        s2 += v * v;
    }
    float invC = 1.0f / (float)C;
    float mean = s * invC;
    float var = s2 * invC - mean * mean;
    mu[m] = mean;
    rs[m] = rsqrtf(var + LN_EPS);
}

// ---------------------------------------------------------------------------
// NCHW -> row-major normalized [NTOK, C] in half
// ---------------------------------------------------------------------------
__global__ void prep_a_kernel(const float* __restrict__ x, int C,
                              const float* __restrict__ mu,
                              const float* __restrict__ rs,
                              __half* __restrict__ Arow) {
    __shared__ float t[32][33];
    int b = blockIdx.z;
    int hw0 = blockIdx.x * 32;
    int c0 = blockIdx.y * 32;
    int tx = threadIdx.x, ty = threadIdx.y;  // 32 x 8
#pragma unroll
    for (int q = 0; q < 4; q++)
        t[ty + q * 8][tx] = x[(((size_t)(b * C + c0 + ty + q * 8)) << 12) + hw0 + tx];
    __syncthreads();
#pragma unroll
    for (int q = 0; q < 4; q++) {
        int m = b * 4096 + hw0 + ty + q * 8;
        float v = (t[tx][ty + q * 8] - mu[m]) * rs[m];
        Arow[(size_t)m * C + c0 + tx] = __float2half_rn(v);
    }
}

// ---------------------------------------------------------------------------
// Weight prep: W [K,N] -> Bt half [N][BK] at column offset koff, *lnw[k]
// ---------------------------------------------------------------------------
__global__ void prep_w_kernel(const float* __restrict__ W, int K, int N,
                              const float* __restrict__ lnw,
                              __half* __restrict__ Bt, int BK, int koff) {
    __shared__ float t[32][33];
    int k0 = blockIdx.x * 32;
    int n0 = blockIdx.y * 32;
    int tx = threadIdx.x, ty = threadIdx.y;
#pragma unroll
    for (int q = 0; q < 4; q++)
        t[ty + q * 8][tx] = W[(size_t)(k0 + ty + q * 8) * N + n0 + tx];
    __syncthreads();
#pragma unroll
    for (int q = 0; q < 4; q++) {
        int k = k0 + tx;
        float s = lnw ? lnw[k] : 1.0f;
        Bt[(size_t)(n0 + ty + q * 8) * BK + koff + k] =
            __float2half_rn(t[tx][ty + q * 8] * s);
    }
}

// Wsc is [N=256, K=384]; scale each row by BN scale
__global__ void prep_wsc_kernel(const float* __restrict__ Wsc,
                                const float* __restrict__ g,
                                const float* __restrict__ v,
                                __half* __restrict__ Bt) {
    int idx = blockIdx.x * blockDim.x + threadIdx.x;
    if (idx >= 256 * 384) return;
    int n = idx / 384;
    float s = rsqrtf(v[n] + LN_EPS) * g[n];
    Bt[idx] = __float2half_rn(Wsc[idx] * s);
}

// addb[n] = sum_k lnb[k]*W[k,n]
__global__ void prep_bias_kernel(const float* __restrict__ W, int K, int N,
                                 const float* __restrict__ lnb,
                                 float* __restrict__ addb) {
    int n = blockIdx.x * blockDim.x + threadIdx.x;
    if (n >= N) return;
    float s = 0.f;
    for (int k = 0; k < K; k++) s += lnb[k] * W[(size_t)k * N + n];
    addb[n] = s;
}

__global__ void prep_sc_bias_kernel(const float* __restrict__ Wsc,
                                    const float* __restrict__ g,
                                    const float* __restrict__ bta,
                                    const float* __restrict__ mn,
                                    const float* __restrict__ vr,
                                    float* __restrict__ addb,
                                    float* __restrict__ wsum) {
    int n = threadIdx.x;
    if (n >= 256) return;
    float s = rsqrtf(vr[n] + LN_EPS) * g[n];
    addb[n] = bta[n] - mn[n] * s;
    float ws = 0.f;
    for (int k = 0; k < 384; k++) ws += Wsc[(size_t)n * 384 + k];
    wsum[n] = ws * s;
}

__global__ void prep_vboc_kernel(const float* __restrict__ b1,
                                 const float* __restrict__ b2,
                                 float* __restrict__ o) {
    int n = threadIdx.x;
    o[n] = b1[n] + b2[n];
}

// ---------------------------------------------------------------------------
// fp16 mma GEMM: C[M,NC] tile(128x128) = A[M,K](half) @ Bt[NC,K](half)^T
// 8 warps, warp tile 32x64, m16n8k16, KC=32, 2-stage cp.async.
// EPI 0: Ch = half(D + addb[n])                      (P projections)
// EPI 1: Cf = D/rs[m] + mu[m]*wsum[n] + addb[n] + xg (shortcut init)
// EPI 2: Cf += D + addb[n]                           (combined out-proj)
// ---------------------------------------------------------------------------
#define SH 40   // smem halfs per row (32 data + 8 pad)

template <int EPI>
__global__ __launch_bounds__(256, 2)
void hgemm(const __half* __restrict__ A, const __half* __restrict__ Bt,
           void* __restrict__ Cv, int K, int NC,
           const float* __restrict__ addb,
           const float* __restrict__ mu, const float* __restrict__ rs,
           const float* __restrict__ wsum, const float* __restrict__ xg) {
    __shared__ __align__(16) __half sAB[2][2][128 * SH];

    const int tid = threadIdx.x;
    const int warp = tid >> 5, lane = tid & 31;
    const int wm = warp >> 1, wn = warp & 1;
    const int g = lane >> 2, t4 = lane & 3;
    const int n0 = blockIdx.x * 128;
    const int m0 = blockIdx.y * 128;

    const __half* Abase = A + (size_t)m0 * K;
    const __half* Bbase = Bt + (size_t)n0 * K;

    const int lr = tid >> 1;            // row 0..127
    const int lq = (tid & 1) << 4;      // k offset 0 or 16

    uint32_t sAaddr[2], sBaddr[2];
    sAaddr[0] = smem_u32(&sAB[0][0][0]);
    sAaddr[1] = smem_u32(&sAB[1][0][0]);
    sBaddr[0] = smem_u32(&sAB[0][1][0]);
    sBaddr[1] = smem_u32(&sAB[1][1][0]);

    float acc[2][8][4];
#pragma unroll
    for (int mt = 0; mt < 2; mt++)
#pragma unroll
        for (int nt = 0; nt < 8; nt++)
#pragma unroll
            for (int u = 0; u < 4; u++) acc[mt][nt][u] = 0.f;

    const int nch = K >> 5;

    // prologue
    cp16(sAaddr[0] + (uint32_t)(lr * SH + lq) * 2, Abase + (size_t)lr * K + lq);
    cp16(sAaddr[0] + (uint32_t)(lr * SH + lq + 8) * 2, Abase + (size_t)lr * K + lq + 8);
    cp16(sBaddr[0] + (uint32_t)(lr * SH + lq) * 2, Bbase + (size_t)lr * K + lq);
    cp16(sBaddr[0] + (uint32_t)(lr * SH + lq + 8) * 2, Bbase + (size_t)lr * K + lq + 8);
    asm volatile("cp.async.commit_group;" ::: "memory");

    for (int ch = 0; ch < nch; ch++) {
        const int st = ch & 1;
        if (ch + 1 < nch) {
            const int k0 = (ch + 1) << 5;
            const int st2 = st ^ 1;
            cp16(sAaddr[st2] + (uint32_t)(lr * SH + lq) * 2,
                 Abase + (size_t)lr * K + k0 + lq);
            cp16(sAaddr[st2] + (uint32_t)(lr * SH + lq + 8) * 2,
                 Abase + (size_t)lr * K + k0 + lq + 8);
            cp16(sBaddr[st2] + (uint32_t)(lr * SH + lq) * 2,
                 Bbase + (size_t)lr * K + k0 + lq);
            cp16(sBaddr[st2] + (uint32_t)(lr * SH + lq + 8) * 2,
                 Bbase + (size_t)lr * K + k0 + lq + 8);
            asm volatile("cp.async.commit_group;" ::: "memory");
            asm volatile("cp.async.wait_group 1;" ::: "memory");
        } else {
            asm volatile("cp.async.wait_group 0;" ::: "memory");
        }
        __syncthreads();

        const __half* a_s = sAB[st][0];
        const __half* b_s = sAB[st][1];
#pragma unroll
        for (int kk = 0; kk < 2; kk++) {
            const int kb = (kk << 4) + 2 * t4;
            uint32_t af[2][4];
#pragma unroll
            for (int mt = 0; mt < 2; mt++) {
                int m = wm * 32 + mt * 16 + g;
                af[mt][0] = *(const uint32_t*)&a_s[m * SH + kb];
                af[mt][1] = *(const uint32_t*)&a_s[(m + 8) * SH + kb];
                af[mt][2] = *(const uint32_t*)&a_s[m * SH + kb + 8];
                af[mt][3] = *(const uint32_t*)&a_s[(m + 8) * SH + kb + 8];
            }
            uint32_t bf[8][2];
#pragma unroll
            for (int nt = 0; nt < 8; nt++) {
                int n = wn * 64 + nt * 8 + g;
                bf[nt][0] = *(const uint32_t*)&b_s[n * SH + kb];
                bf[nt][1] = *(const uint32_t*)&b_s[n * SH + kb + 8];
            }
#pragma unroll
            for (int mt = 0; mt < 2; mt++)
#pragma unroll
                for (int nt = 0; nt < 8; nt++)
                    mma_f16(acc[mt][nt], af[mt], bf[nt][0], bf[nt][1]);
        }
        __syncthreads();
    }

    // ---- epilogue ----
    const int r0base = m0 + wm * 32 + g;
    const int cbase = n0 + wn * 64 + 2 * t4;

    if (EPI == 0) {
        __half* Ch = (__half*)Cv;
#pragma unroll
        for (int mt = 0; mt < 2; mt++) {
            int r0 = r0base + mt * 16;
#pragma unroll
            for (int nt = 0; nt < 8; nt++) {
                int cn = cbase + nt * 8;
                float b0 = addb[cn], b1 = addb[cn + 1];
                *(__half2*)&Ch[(size_t)r0 * NC + cn] =
                    __floats2half2_rn(acc[mt][nt][0] + b0, acc[mt][nt][1] + b1);
                *(__half2*)&Ch[(size_t)(r0 + 8) * NC + cn] =
                    __floats2half2_rn(acc[mt][nt][2] + b0, acc[mt][nt][3] + b1);
            }
        }
    } else if (EPI == 1) {
        float* C = (float*)Cv;
#pragma unroll
        for (int mt = 0; mt < 2; mt++) {
            int r0 = r0base + mt * 16;
            int r1 = r0 + 8;
            float i0 = 1.0f / rs[r0], m0v = mu[r0];
            float i1 = 1.0f / rs[r1], m1v = mu[r1];
            int b0i = r0 >> 12, hw0 = r0 & 4095;
            int b1i = r1 >> 12, hw1 = r1 & 4095;
#pragma unroll
            for (int nt = 0; nt < 8; nt++) {
                int cn = cbase + nt * 8;
                float a0 = addb[cn], a1 = addb[cn + 1];
                float w0 = wsum[cn], w1 = wsum[cn + 1];
                float2 v0, v1;
                v0.x = acc[mt][nt][0] * i0 + m0v * w0 + a0 +
                       xg[(((size_t)((b0i << 8) + cn)) << 12) + hw0];
                v0.y = acc[mt][nt][1] * i0 + m0v * w1 + a1 +
                       xg[(((size_t)((b0i << 8) + cn + 1)) << 12) + hw0];
                v1.x = acc[mt][nt][2] * i1 + m1v * w0 + a0 +
                       xg[(((size_t)((b1i << 8) + cn)) << 12) + hw1];
                v1.y = acc[mt][nt][3] * i1 + m1v * w1 + a1 +
                       xg[(((size_t)((b1i << 8) + cn + 1)) << 12) + hw1];
                *(float2*)&C[(size_t)r0 * NC + cn] = v0;
                *(float2*)&C[(size_t)r1 * NC + cn] = v1;
            }
        }
    } else {  // EPI == 2
        float* C = (float*)Cv;
#pragma unroll
        for (int mt = 0; mt < 2; mt++) {
            int r0 = r0base + mt * 16;
#pragma unroll
            for (int nt = 0; nt < 8; nt++) {
                int cn = cbase + nt * 8;
                float b0 = addb[cn], b1 = addb[cn + 1];
                float2 o0 = *(const float2*)&C[(size_t)r0 * NC + cn];
                float2 o1 = *(const float2*)&C[(size_t)(r0 + 8) * NC + cn];
                o0.x += acc[mt][nt][0] + b0;
                o0.y += acc[mt][nt][1] + b1;
                o1.x += acc[mt][nt][2] + b0;
                o1.y += acc[mt][nt][3] + b1;
                *(float2*)&C[(size_t)r0 * NC + cn] = o0;
                *(float2*)&C[(size_t)(r0 + 8) * NC + cn] = o1;
            }
        }
    }
}

// ---------------------------------------------------------------------------
// mma-based axial attention.
// Block: 256 thr = 8 warps, handles one (branch, b, x, head-pair) line of 64
// tokens for 2 heads. Warp w: head hl=w>>2, row-block mb=w&3 (16 rows).
// P layout [NTOK,768] half: q 0..255 | k 256..511 | v 512..767.
// O layout [NTOK,512] half: branch0 cols 0..255, branch1 cols 256..511.
// axis0 pass writes O; axis1 pass accumulates.
// ---------------------------------------------------------------------------
__global__ __launch_bounds__(256)
void attn_mma_kernel(const __half* __restrict__ P1, const __half* __restrict__ P2,
                     __half* __restrict__ O, int axis) {
    __shared__ __align__(16) __half qs[64][72];
    __shared__ __align__(16) __half ks[64][72];
    __shared__ __align__(16) __half vs[64][72];

    const int tid = threadIdx.x;
    const int warp = tid >> 5, lane = tid & 31;
    const int g = lane >> 2, t4 = lane & 3;

    const int bx = blockIdx.x;
    const int branch = bx >> 11;
    const int idx = bx & 2047;
    const int b = idx >> 8;
    const int rem = idx & 255;
    const int x = rem >> 2;
    const int hp = rem & 3;

    const __half* Pq = branch ? P2 : P1;
    const __half* Pkv = branch ? P1 : P2;
    const int boff = branch << 8;
    const int base = b * 4096 + (axis ? x * 64 : x);
    const int step = axis ? 1 : 64;

    // ---- load 64 tokens x 64 halfs (2 heads) for q, k, v ----
    {
        const int lrow = tid >> 2;
        const int lseg = (tid & 3) << 4;
        size_t trow = (size_t)(base + lrow * step) * 768;
        const uint4* qp = (const uint4*)(Pq + trow + hp * 64 + lseg);
        *(uint4*)&qs[lrow][lseg] = qp[0];
        *(uint4*)&qs[lrow][lseg + 8] = qp[1];
        const uint4* kp = (const uint4*)(Pkv + trow + 256 + hp * 64 + lseg);
        *(uint4*)&ks[lrow][lseg] = kp[0];
        *(uint4*)&ks[lrow][lseg + 8] = kp[1];
        const uint4* vp = (const uint4*)(Pkv + trow + 512 + hp * 64 + lseg);
        *(uint4*)&vs[lrow][lseg] = vp[0];
        *(uint4*)&vs[lrow][lseg + 8] = vp[1];
    }
    __syncthreads();

    const int hl = warp >> 2;     // head within pair
    const int mb = warp & 3;      // row block
    const int hq = hl << 5;       // smem col base
    const int r1 = mb * 16 + g;
    const int r2 = r1 + 8;

    // ---- S = Q @ K^T  (fp32 accum) ----
    uint32_t a[2][4];
#pragma unroll
    for (int kk = 0; kk < 2; kk++) {
        int kb = hq + (kk << 4) + 2 * t4;
        a[kk][0] = *(const uint32_t*)&qs[r1][kb];
        a[kk][1] = *(const uint32_t*)&qs[r2][kb];
        a[kk][2] = *(const uint32_t*)&qs[r1][kb + 8];
        a[kk][3] = *(const uint32_t*)&qs[r2][kb + 8];
    }
    float sc[8][4];
#pragma unroll
    for (int nt = 0; nt < 8; nt++) {
#pragma unroll
        for (int u = 0; u < 4; u++) sc[nt][u] = 0.f;
        int kr = nt * 8 + g;
#pragma unroll
        for (int kk = 0; kk < 2; kk++) {
            int kb = hq + (kk << 4) + 2 * t4;
            uint32_t b0 = *(const uint32_t*)&ks[kr][kb];
            uint32_t b1 = *(const uint32_t*)&ks[kr][kb + 8];
            mma_f16(sc[nt], a[kk], b0, b1);
        }
    }

    // ---- softmax over 64 cols (rows r1, r2) ----
    float mx1 = -1e30f, mx2 = -1e30f;
#pragma unroll
    for (int nt = 0; nt < 8; nt++) {
        mx1 = fmaxf(mx1, fmaxf(sc[nt][0], sc[nt][1]));
        mx2 = fmaxf(mx2, fmaxf(sc[nt][2], sc[nt][3]));
    }
    mx1 = fmaxf(mx1, __shfl_xor_sync(0xffffffffu, mx1, 1));
    mx1 = fmaxf(mx1, __shfl_xor_sync(0xffffffffu, mx1, 2));
    mx2 = fmaxf(mx2, __shfl_xor_sync(0xffffffffu, mx2, 1));
    mx2 = fmaxf(mx2, __shfl_xor_sync(0xffffffffu, mx2, 2));

    const float cexp = 0.17677669529663687f * 1.4426950408889634f;
    float s1 = 0.f, s2 = 0.f;
#pragma unroll
    for (int nt = 0; nt < 8; nt++) {
        sc[nt][0] = fexp2((sc[nt][0] - mx1) * cexp);
        sc[nt][1] = fexp2((sc[nt][1] - mx1) * cexp);
        sc[nt][2] = fexp2((sc[nt][2] - mx2) * cexp);
        sc[nt][3] = fexp2((sc[nt][3] - mx2) * cexp);
        s1 += sc[nt][0] + sc[nt][1];
        s2 += sc[nt][2] + sc[nt][3];
    }
    s1 += __shfl_xor_sync(0xffffffffu, s1, 1);
    s1 += __shfl_xor_sync(0xffffffffu, s1, 2);
    s2 += __shfl_xor_sync(0xffffffffu, s2, 1);
    s2 += __shfl_xor_sync(0xffffffffu, s2, 2);
    const float inv1 = 1.0f / s1;
    const float inv2 = 1.0f / s2;

    // ---- O = P @ V  (P fragments reused in-register, V via ldmatrix.trans) ----
    float od[4][4];
#pragma unroll
    for (int nt2 = 0; nt2 < 4; nt2++)
#pragma unroll
        for (int u = 0; u < 4; u++) od[nt2][u] = 0.f;

#pragma unroll
    for (int ks2 = 0; ks2 < 4; ks2++) {
        uint32_t pa[4];
        {
            __half2 h;
            h = __floats2half2_rn(sc[2 * ks2][0], sc[2 * ks2][1]);
            pa[0] = *(uint32_t*)&h;
            h = __floats2half2_rn(sc[2 * ks2][2], sc[2 * ks2][3]);
            pa[1] = *(uint32_t*)&h;
            h = __floats2half2_rn(sc[2 * ks2 + 1][0], sc[2 * ks2 + 1][1]);
            pa[2] = *(uint32_t*)&h;
            h = __floats2half2_rn(sc[2 * ks2 + 1][2], sc[2 * ks2 + 1][3]);
            pa[3] = *(uint32_t*)&h;
        }
        const int k0 = ks2 << 4;
#pragma unroll
        for (int pp = 0; pp < 2; pp++) {
            // ldmatrix.x4.trans: mats = (k0..k0+15) x cols {d0, d0+8}
            int vrow = k0 + (lane & 15);
            int vcol = hq + (pp << 4) + ((lane >> 4) << 3);
            uint32_t addr = smem_u32(&vs[vrow][vcol]);
            uint32_t v0, v1, v2, v3;
            asm volatile(
                "ldmatrix.sync.aligned.m8n8.x4.trans.shared.b16 {%0,%1,%2,%3}, [%4];"
                : "=r"(v0), "=r"(v1), "=r"(v2), "=r"(v3) : "r"(addr));
            mma_f16(od[2 * pp], pa, v0, v1);
            mma_f16(od[2 * pp + 1], pa, v2, v3);
        }
    }

    // ---- write O ----
    const size_t t1 = (size_t)(base + r1 * step);
    const size_t t2 = (size_t)(base + r2 * step);
    const int colb = boff + (hp << 6) + (hl << 5) + 2 * t4;
#pragma unroll
    for (int nt2 = 0; nt2 < 4; nt2++) {
        int col = colb + nt2 * 8;
        __half2* p1o = (__half2*)&O[t1 * 512 + col];
        __half2* p2o = (__half2*)&O[t2 * 512 + col];
        float c0 = od[nt2][0] * inv1, c1 = od[nt2][1] * inv1;
        float c2 = od[nt2][2] * inv2, c3 = od[nt2][3] * inv2;
        if (axis == 0) {
            *p1o = __floats2half2_rn(c0, c1);
            *p2o = __floats2half2_rn(c2, c3);
        } else {
            float2 f1 = __half22float2(*p1o);
            float2 f2 = __half22float2(*p2o);
            *p1o = __floats2half2_rn(f1.x + c0, f1.y + c1);
            *p2o = __floats2half2_rn(f2.x + c2, f2.y + c3);
        }
    }
}

// ---------------------------------------------------------------------------
// Final transpose: acc [token, 256] f32 -> out [B, 256, H, W]
// ---------------------------------------------------------------------------
__global__ void transpose_out_kernel(const float* __restrict__ acc,
                                     float* __restrict__ out) {
    __shared__ float t[32][33];
    int b = blockIdx.z;
    int hw0 = blockIdx.x * 32;
    int c0 = blockIdx.y * 32;
    int tx = threadIdx.x, ty = threadIdx.y;
#pragma unroll
    for (int q = 0; q < 4; q++)
        t[ty + q * 8][tx] =
            acc[((size_t)b * 4096 + hw0 + ty + q * 8) * 256 + c0 + tx];
    __syncthreads();
#pragma unroll
    for (int q = 0; q < 4; q++)
        out[(((size_t)(b * 256 + c0 + ty + q * 8)) << 12) + hw0 + tx] =
            t[tx][ty + q * 8];
}

// ---------------------------------------------------------------------------
// Launch
// ---------------------------------------------------------------------------
extern "C" void kernel_launch(void* const* d_in, const int* in_sizes, int n_in,
                              void* d_out, int out_size) {
    const float* x1     = (const float*)d_in[0];
    const float* x2     = (const float*)d_in[1];
    const float* ln1q_w = (const float*)d_in[2];
    const float* ln1q_b = (const float*)d_in[3];
    const float* ln2kv_w= (const float*)d_in[4];
    const float* ln2kv_b= (const float*)d_in[5];
    const float* Wq1    = (const float*)d_in[6];
    const float* Wkv2   = (const float*)d_in[7];
    const float* Wout1  = (const float*)d_in[8];
    const float* bout1  = (const float*)d_in[9];
    const float* ln2q_w = (const float*)d_in[10];
    const float* ln2q_b = (const float*)d_in[11];
    const float* ln1kv_w= (const float*)d_in[12];
    const float* ln1kv_b= (const float*)d_in[13];
    const float* Wq2    = (const float*)d_in[14];
    const float* Wkv1   = (const float*)d_in[15];
    const float* Wout2  = (const float*)d_in[16];
    const float* bout2  = (const float*)d_in[17];
    const float* Wsc    = (const float*)d_in[18];
    const float* bng    = (const float*)d_in[19];
    const float* bnb    = (const float*)d_in[20];
    const float* bnm    = (const float*)d_in[21];
    const float* bnv    = (const float*)d_in[22];
    float* out = (float*)d_out;

    float* S = nullptr;
    cudaGetSymbolAddress((void**)&S, g_scratch);
    float* mu1  = S + OFF_MU1;  float* rs1 = S + OFF_RS1;
    float* mu2  = S + OFF_MU2;  float* rs2 = S + OFF_RS2;
    __half* A1h = (__half*)(S + OFF_A1H);
    __half* A2h = (__half*)(S + OFF_A2H);
    __half* B1h = (__half*)(S + OFF_B1H);
    __half* B2h = (__half*)(S + OFF_B2H);
    __half* BscH= (__half*)(S + OFF_BSCH);
    __half* BoCH= (__half*)(S + OFF_BOCH);
    float* vb1  = S + OFF_VB1;  float* vb2 = S + OFF_VB2;
    float* vboc = S + OFF_VBOC; float* vbsc= S + OFF_VBSC;
    float* wsum = S + OFF_WSUM;
    __half* P1h = (__half*)(S + OFF_P1);
    __half* P2h = (__half*)(S + OFF_P2);
    __half* Oh  = (__half*)(S + OFF_OH);
    float* accb = S + OFF_ACC;

    dim3 tb(32, 8);

    // 1) stats + normalized-A preps (half)
    ln_stats_kernel<<<NTOK / 256, 256>>>(x1, DIM1, mu1, rs1);
    ln_stats_kernel<<<NTOK / 256, 256>>>(x2, DIM2, mu2, rs2);
    prep_a_kernel<<<dim3(128, 12, 8), tb>>>(x1, DIM1, mu1, rs1, A1h);
    prep_a_kernel<<<dim3(128, 8, 8), tb>>>(x2, DIM2, mu2, rs2, A2h);

    // 2) weight preps: B1h = [q1|kv1] (K=384), B2h = [q2|kv2] (K=256),
    //    BoCH = [Wout1;Wout2] (N=256, K=512)
    prep_w_kernel<<<dim3(12, 8), tb>>>(Wq1, 384, 256, ln1q_w, B1h, 384, 0);
    prep_w_kernel<<<dim3(12, 16), tb>>>(Wkv1, 384, 512, ln1kv_w, B1h + 256 * 384, 384, 0);
    prep_w_kernel<<<dim3(8, 8), tb>>>(Wq2, 256, 256, ln2q_w, B2h, 256, 0);
    prep_w_kernel<<<dim3(8, 16), tb>>>(Wkv2, 256, 512, ln2kv_w, B2h + 256 * 256, 256, 0);
    prep_w_kernel<<<dim3(8, 8), tb>>>(Wout1, 256, 256, nullptr, BoCH, 512, 0);
    prep_w_kernel<<<dim3(8, 8), tb>>>(Wout2, 256, 256, nullptr, BoCH, 512, 256);
    prep_wsc_kernel<<<384, 256>>>(Wsc, bng, bnv, BscH);
    prep_bias_kernel<<<1, 256>>>(Wq1, 384, 256, ln1q_b, vb1);
    prep_bias_kernel<<<2, 256>>>(Wkv1, 384, 512, ln1kv_b, vb1 + 256);
    prep_bias_kernel<<<1, 256>>>(Wq2, 256, 256, ln2q_b, vb2);
    prep_bias_kernel<<<2, 256>>>(Wkv2, 256, 512, ln2kv_b, vb2 + 256);
    prep_sc_bias_kernel<<<1, 256>>>(Wsc, bng, bnb, bnm, bnv, vbsc, wsum);
    prep_vboc_kernel<<<1, 256>>>(bout1, bout2, vboc);

    // 3) fused projections (half in, half out)
    hgemm<0><<<dim3(6, 256), 256>>>(A1h, B1h, P1h, 384, 768, vb1,
                                    nullptr, nullptr, nullptr, nullptr);
    hgemm<0><<<dim3(6, 256), 256>>>(A2h, B2h, P2h, 256, 768, vb2,
                                    nullptr, nullptr, nullptr, nullptr);

    // 4) shortcut GEMM -> acc = BN(x1f@Wsc^T) + x2f   (fp32 out)
    hgemm<1><<<dim3(2, 256), 256>>>(A1h, BscH, accb, 384, 256, vbsc,
                                    mu1, rs1, wsum, x2);

    // 5) mma axial attention: axis0 writes O, axis1 accumulates
    attn_mma_kernel<<<4096, 256>>>(P1h, P2h, Oh, 0);
    attn_mma_kernel<<<4096, 256>>>(P1h, P2h, Oh, 1);

    // 6) combined output projection: acc += [o1|o2] @ [Wout1;Wout2] + biases
    hgemm<2><<<dim3(2, 256), 256>>>(Oh, BoCH, accb, 512, 256, vboc,
                                    nullptr, nullptr, nullptr, nullptr);

    // 7) NHWC -> NCHW
    transpose_out_kernel<<<dim3(128, 8, 8), tb>>>(accb, out);
}

// round 17
// speedup vs baseline: 2.4799x; 1.0263x over previous
#include <cuda_runtime.h>
#include <cuda_fp16.h>
#include <cstdint>
#include <cstddef>

// ---------------------------------------------------------------------------
// Problem constants
// ---------------------------------------------------------------------------
#define BATCH 8
#define DIM1 384
#define DIM2 256
#define NTOK 32768
#define LN_EPS 1e-5f

// ---------------------------------------------------------------------------
// Helpers (baseline PTX only: mma.sync fp16, ldmatrix, cp.async — no tcgen05)
// ---------------------------------------------------------------------------
__device__ __forceinline__ uint32_t smem_u32(const void* p) {
    uint32_t a;
    asm("{ .reg .u64 t; cvta.to.shared.u64 t, %1; cvt.u32.u64 %0, t; }"
        : "=r"(a) : "l"(p));
    return a;
}
__device__ __forceinline__ void cp16(uint32_t s, const void* g) {
    asm volatile("cp.async.cg.shared.global [%0], [%1], 16;" :: "r"(s), "l"(g));
}
__device__ __forceinline__ void mma_f16(float* c, const uint32_t* a,
                                        uint32_t b0, uint32_t b1) {
    asm volatile(
        "mma.sync.aligned.m16n8k16.row.col.f32.f16.f16.f32 "
        "{%0,%1,%2,%3}, {%4,%5,%6,%7}, {%8,%9}, {%0,%1,%2,%3};"
        : "+f"(c[0]), "+f"(c[1]), "+f"(c[2]), "+f"(c[3])
        : "r"(a[0]), "r"(a[1]), "r"(a[2]), "r"(a[3]), "r"(b0), "r"(b1));
}
#define LDMX4(r0, r1, r2, r3, addr) \
    asm volatile("ldmatrix.sync.aligned.m8n8.x4.shared.b16 {%0,%1,%2,%3}, [%4];" \
                 : "=r"(r0), "=r"(r1), "=r"(r2), "=r"(r3) : "r"(addr))
__device__ __forceinline__ float fexp2(float x) {
    float r;
    asm("ex2.approx.f32 %0, %1;" : "=f"(r) : "f"(x));
    return r;
}

// ---------------------------------------------------------------------------
// Scratch layout (units: floats; half regions use 2 halfs per float slot)
// ---------------------------------------------------------------------------
constexpr size_t OFF_MU1  = 0;
constexpr size_t OFF_RS1  = OFF_MU1 + NTOK;
constexpr size_t OFF_MU2  = OFF_RS1 + NTOK;
constexpr size_t OFF_RS2  = OFF_MU2 + NTOK;
constexpr size_t OFF_A1H  = OFF_RS2 + NTOK;                     // 32768*384 h
constexpr size_t OFF_A2H  = OFF_A1H + (size_t)NTOK * DIM1 / 2;  // 32768*256 h
constexpr size_t OFF_B1H  = OFF_A2H + (size_t)NTOK * DIM2 / 2;  // 768*384 h
constexpr size_t OFF_B2H  = OFF_B1H + 768 * 384 / 2;            // 768*256 h
constexpr size_t OFF_BSCH = OFF_B2H + 768 * 256 / 2;            // 256*384 h
constexpr size_t OFF_BOCH = OFF_BSCH + 256 * 384 / 2;           // 256*512 h
constexpr size_t OFF_VB1  = OFF_BOCH + 256 * 512 / 2;           // 768 f
constexpr size_t OFF_VB2  = OFF_VB1 + 768;                      // 768 f
constexpr size_t OFF_VBOC = OFF_VB2 + 768;                      // 256 f
constexpr size_t OFF_VBSC = OFF_VBOC + 256;                     // 256 f
constexpr size_t OFF_WSUM = OFF_VBSC + 256;                     // 256 f
constexpr size_t OFF_P1   = OFF_WSUM + 256;                     // 32768*768 h
constexpr size_t OFF_P2   = OFF_P1 + (size_t)NTOK * 768 / 2;
constexpr size_t OFF_OH   = OFF_P2 + (size_t)NTOK * 768 / 2;    // 32768*512 h
constexpr size_t OFF_ACC  = OFF_OH + (size_t)NTOK * 512 / 2;    // 32768*256 f
constexpr size_t SCRATCH_TOTAL = OFF_ACC + (size_t)NTOK * 256;

__device__ __align__(128) float g_scratch[SCRATCH_TOTAL];

// ---------------------------------------------------------------------------
// LN stats per token
// ---------------------------------------------------------------------------
__global__ void ln_stats_kernel(const float* __restrict__ x, int C,
                                float* __restrict__ mu, float* __restrict__ rs) {
    int m = blockIdx.x * blockDim.x + threadIdx.x;
    int b = m >> 12;
    int hw = m & 4095;
    const float* p = x + ((size_t)b * C << 12) + hw;
    float s = 0.f, s2 = 0.f;
    for (int c = 0; c < C; c++) {
        float v = p[(size_t)c << 12];
        s += v;
        s2 += v * v;
    }
    float invC = 1.0f / (float)C;
    float mean = s * invC;
    float var = s2 * invC - mean * mean;
    mu[m] = mean;
    rs[m] = rsqrtf(var + LN_EPS);
}

// ---------------------------------------------------------------------------
// NCHW -> row-major normalized [NTOK, C] in half
// ---------------------------------------------------------------------------
__global__ void prep_a_kernel(const float* __restrict__ x, int C,
                              const float* __restrict__ mu,
                              const float* __restrict__ rs,
                              __half* __restrict__ Arow) {
    __shared__ float t[32][33];
    int b = blockIdx.z;
    int hw0 = blockIdx.x * 32;
    int c0 = blockIdx.y * 32;
    int tx = threadIdx.x, ty = threadIdx.y;  // 32 x 8
#pragma unroll
    for (int q = 0; q < 4; q++)
        t[ty + q * 8][tx] = x[(((size_t)(b * C + c0 + ty + q * 8)) << 12) + hw0 + tx];
    __syncthreads();
#pragma unroll
    for (int q = 0; q < 4; q++) {
        int m = b * 4096 + hw0 + ty + q * 8;
        float v = (t[tx][ty + q * 8] - mu[m]) * rs[m];
        Arow[(size_t)m * C + c0 + tx] = __float2half_rn(v);
    }
}

// ---------------------------------------------------------------------------
// Weight prep: W [K,N] -> Bt half [N][BK] at column offset koff, *lnw[k]
// ---------------------------------------------------------------------------
__global__ void prep_w_kernel(const float* __restrict__ W, int K, int N,
                              const float* __restrict__ lnw,
                              __half* __restrict__ Bt, int BK, int koff) {
    __shared__ float t[32][33];
    int k0 = blockIdx.x * 32;
    int n0 = blockIdx.y * 32;
    int tx = threadIdx.x, ty = threadIdx.y;
#pragma unroll
    for (int q = 0; q < 4; q++)
        t[ty + q * 8][tx] = W[(size_t)(k0 + ty + q * 8) * N + n0 + tx];
    __syncthreads();
#pragma unroll
    for (int q = 0; q < 4; q++) {
        int k = k0 + tx;
        float s = lnw ? lnw[k] : 1.0f;
        Bt[(size_t)(n0 + ty + q * 8) * BK + koff + k] =
            __float2half_rn(t[tx][ty + q * 8] * s);
    }
}

// Wsc is [N=256, K=384]; scale each row by BN scale
__global__ void prep_wsc_kernel(const float* __restrict__ Wsc,
                                const float* __restrict__ g,
                                const float* __restrict__ v,
                                __half* __restrict__ Bt) {
    int idx = blockIdx.x * blockDim.x + threadIdx.x;
    if (idx >= 256 * 384) return;
    int n = idx / 384;
    float s = rsqrtf(v[n] + LN_EPS) * g[n];
    Bt[idx] = __float2half_rn(Wsc[idx] * s);
}

// addb[n] = sum_k lnb[k]*W[k,n]
__global__ void prep_bias_kernel(const float* __restrict__ W, int K, int N,
                                 const float* __restrict__ lnb,
                                 float* __restrict__ addb) {
    int n = blockIdx.x * blockDim.x + threadIdx.x;
    if (n >= N) return;
    float s = 0.f;
    for (int k = 0; k < K; k++) s += lnb[k] * W[(size_t)k * N + n];
    addb[n] = s;
}

__global__ void prep_sc_bias_kernel(const float* __restrict__ Wsc,
                                    const float* __restrict__ g,
                                    const float* __restrict__ bta,
                                    const float* __restrict__ mn,
                                    const float* __restrict__ vr,
                                    float* __restrict__ addb,
                                    float* __restrict__ wsum) {
    int n = threadIdx.x;
    if (n >= 256) return;
    float s = rsqrtf(vr[n] + LN_EPS) * g[n];
    addb[n] = bta[n] - mn[n] * s;
    float ws = 0.f;
    for (int k = 0; k < 384; k++) ws += Wsc[(size_t)n * 384 + k];
    wsum[n] = ws * s;
}

__global__ void prep_vboc_kernel(const float* __restrict__ b1,
                                 const float* __restrict__ b2,
                                 float* __restrict__ o) {
    int n = threadIdx.x;
    o[n] = b1[n] + b2[n];
}

// ---------------------------------------------------------------------------
// fp16 mma GEMM: C[M,NC] tile(128x128) = A[M,K](half) @ Bt[NC,K](half)^T
// 8 warps, warp tile 32x64, m16n8k16, KC=32, 2-stage cp.async, ldmatrix frags.
// EPI 0: Ch = half(D + addb[n])                      (P projections)
// EPI 1: Cf = D/rs[m] + mu[m]*wsum[n] + addb[n]      (shortcut init, no xg)
// EPI 2: Cf += D + addb[n]                           (combined out-proj)
// ---------------------------------------------------------------------------
#define SH 40   // smem halfs per row (32 data + 8 pad); 80B stride, ldmatrix-safe

template <int EPI>
__global__ __launch_bounds__(256, 2)
void hgemm(const __half* __restrict__ A, const __half* __restrict__ Bt,
           void* __restrict__ Cv, int K, int NC,
           const float* __restrict__ addb,
           const float* __restrict__ mu, const float* __restrict__ rs,
           const float* __restrict__ wsum) {
    __shared__ __align__(16) __half sAB[2][2][128 * SH];

    const int tid = threadIdx.x;
    const int warp = tid >> 5, lane = tid & 31;
    const int wm = warp >> 1, wn = warp & 1;
    const int g = lane >> 2, t4 = lane & 3;
    const int n0 = blockIdx.x * 128;
    const int m0 = blockIdx.y * 128;

    const __half* Abase = A + (size_t)m0 * K;
    const __half* Bbase = Bt + (size_t)n0 * K;

    const int lr = tid >> 1;            // row 0..127
    const int lq = (tid & 1) << 4;      // k offset 0 or 16

    uint32_t sAaddr[2], sBaddr[2];
    sAaddr[0] = smem_u32(&sAB[0][0][0]);
    sAaddr[1] = smem_u32(&sAB[1][0][0]);
    sBaddr[0] = smem_u32(&sAB[0][1][0]);
    sBaddr[1] = smem_u32(&sAB[1][1][0]);

    // ldmatrix lane-address components (element offsets within tile)
    const int arow = (lane & 15);                 // + wm*32 + mt*16
    const int acol = ((lane >> 4) << 3);          // + kk*16
    const int brow = ((lane >> 4) << 3) + (lane & 7);  // + wn*64 + p*16
    const int bcol = (((lane >> 3) & 1) << 3);         // + kk*16

    float acc[2][8][4];
#pragma unroll
    for (int mt = 0; mt < 2; mt++)
#pragma unroll
        for (int nt = 0; nt < 8; nt++)
#pragma unroll
            for (int u = 0; u < 4; u++) acc[mt][nt][u] = 0.f;

    const int nch = K >> 5;

    // prologue
    cp16(sAaddr[0] + (uint32_t)(lr * SH + lq) * 2, Abase + (size_t)lr * K + lq);
    cp16(sAaddr[0] + (uint32_t)(lr * SH + lq + 8) * 2, Abase + (size_t)lr * K + lq + 8);
    cp16(sBaddr[0] + (uint32_t)(lr * SH + lq) * 2, Bbase + (size_t)lr * K + lq);
    cp16(sBaddr[0] + (uint32_t)(lr * SH + lq + 8) * 2, Bbase + (size_t)lr * K + lq + 8);
    asm volatile("cp.async.commit_group;" ::: "memory");

    for (int ch = 0; ch < nch; ch++) {
        const int st = ch & 1;
        if (ch + 1 < nch) {
            const int k0 = (ch + 1) << 5;
            const int st2 = st ^ 1;
            cp16(sAaddr[st2] + (uint32_t)(lr * SH + lq) * 2,
                 Abase + (size_t)lr * K + k0 + lq);
            cp16(sAaddr[st2] + (uint32_t)(lr * SH + lq + 8) * 2,
                 Abase + (size_t)lr * K + k0 + lq + 8);
            cp16(sBaddr[st2] + (uint32_t)(lr * SH + lq) * 2,
                 Bbase + (size_t)lr * K + k0 + lq);
            cp16(sBaddr[st2] + (uint32_t)(lr * SH + lq + 8) * 2,
                 Bbase + (size_t)lr * K + k0 + lq + 8);
            asm volatile("cp.async.commit_group;" ::: "memory");
            asm volatile("cp.async.wait_group 1;" ::: "memory");
        } else {
            asm volatile("cp.async.wait_group 0;" ::: "memory");
        }
        __syncthreads();

        const uint32_t aS = sAaddr[st];
        const uint32_t bS = sBaddr[st];
#pragma unroll
        for (int kk = 0; kk < 2; kk++) {
            const int kc = (kk << 4);
            uint32_t af[2][4];
#pragma unroll
            for (int mt = 0; mt < 2; mt++) {
                uint32_t addr = aS +
                    (uint32_t)((wm * 32 + mt * 16 + arow) * SH + kc + acol) * 2;
                LDMX4(af[mt][0], af[mt][1], af[mt][2], af[mt][3], addr);
            }
#pragma unroll
            for (int p = 0; p < 4; p++) {
                uint32_t addr = bS +
                    (uint32_t)((wn * 64 + (p << 4) + brow) * SH + kc + bcol) * 2;
                uint32_t r0, r1, r2, r3;
                LDMX4(r0, r1, r2, r3, addr);
#pragma unroll
                for (int mt = 0; mt < 2; mt++) {
                    mma_f16(acc[mt][2 * p], af[mt], r0, r1);
                    mma_f16(acc[mt][2 * p + 1], af[mt], r2, r3);
                }
            }
        }
        __syncthreads();
    }

    // ---- epilogue ----
    const int r0base = m0 + wm * 32 + g;
    const int cbase = n0 + wn * 64 + 2 * t4;

    if (EPI == 0) {
        __half* Ch = (__half*)Cv;
#pragma unroll
        for (int mt = 0; mt < 2; mt++) {
            int r0 = r0base + mt * 16;
#pragma unroll
            for (int nt = 0; nt < 8; nt++) {
                int cn = cbase + nt * 8;
                float b0 = addb[cn], b1 = addb[cn + 1];
                *(__half2*)&Ch[(size_t)r0 * NC + cn] =
                    __floats2half2_rn(acc[mt][nt][0] + b0, acc[mt][nt][1] + b1);
                *(__half2*)&Ch[(size_t)(r0 + 8) * NC + cn] =
                    __floats2half2_rn(acc[mt][nt][2] + b0, acc[mt][nt][3] + b1);
            }
        }
    } else if (EPI == 1) {
        float* C = (float*)Cv;
#pragma unroll
        for (int mt = 0; mt < 2; mt++) {
            int r0 = r0base + mt * 16;
            int r1 = r0 + 8;
            float i0 = 1.0f / rs[r0], m0v = mu[r0];
            float i1 = 1.0f / rs[r1], m1v = mu[r1];
#pragma unroll
            for (int nt = 0; nt < 8; nt++) {
                int cn = cbase + nt * 8;
                float a0 = addb[cn], a1 = addb[cn + 1];
                float w0 = wsum[cn], w1 = wsum[cn + 1];
                float2 v0, v1;
                v0.x = acc[mt][nt][0] * i0 + m0v * w0 + a0;
                v0.y = acc[mt][nt][1] * i0 + m0v * w1 + a1;
                v1.x = acc[mt][nt][2] * i1 + m1v * w0 + a0;
                v1.y = acc[mt][nt][3] * i1 + m1v * w1 + a1;
                *(float2*)&C[(size_t)r0 * NC + cn] = v0;
                *(float2*)&C[(size_t)r1 * NC + cn] = v1;
            }
        }
    } else {  // EPI == 2
        float* C = (float*)Cv;
#pragma unroll
        for (int mt = 0; mt < 2; mt++) {
            int r0 = r0base + mt * 16;
#pragma unroll
            for (int nt = 0; nt < 8; nt++) {
                int cn = cbase + nt * 8;
                float b0 = addb[cn], b1 = addb[cn + 1];
                float2 o0 = *(const float2*)&C[(size_t)r0 * NC + cn];
                float2 o1 = *(const float2*)&C[(size_t)(r0 + 8) * NC + cn];
                o0.x += acc[mt][nt][0] + b0;
                o0.y += acc[mt][nt][1] + b1;
                o1.x += acc[mt][nt][2] + b0;
                o1.y += acc[mt][nt][3] + b1;
                *(float2*)&C[(size_t)r0 * NC + cn] = o0;
                *(float2*)&C[(size_t)(r0 + 8) * NC + cn] = o1;
            }
        }
    }
}

// ---------------------------------------------------------------------------
// mma-based axial attention (ldmatrix fragment loads).
// Block: 256 thr = 8 warps, one (branch, b, x, head-pair) line of 64 tokens,
// 2 heads. Warp w: head hl=w>>2, row-block mb=w&3 (16 rows).
// P layout [NTOK,768] half: q 0..255 | k 256..511 | v 512..767.
// O layout [NTOK,512] half: branch0 cols 0..255, branch1 cols 256..511.
// axis0 pass writes O; axis1 pass accumulates.
// ---------------------------------------------------------------------------
__global__ __launch_bounds__(256)
void attn_mma_kernel(const __half* __restrict__ P1, const __half* __restrict__ P2,
                     __half* __restrict__ O, int axis) {
    __shared__ __align__(16) __half qs[64][72];
    __shared__ __align__(16) __half ks[64][72];
    __shared__ __align__(16) __half vs[64][72];

    const int tid = threadIdx.x;
    const int warp = tid >> 5, lane = tid & 31;
    const int g = lane >> 2, t4 = lane & 3;

    const int bx = blockIdx.x;
    const int branch = bx >> 11;
    const int idx = bx & 2047;
    const int b = idx >> 8;
    const int rem = idx & 255;
    const int x = rem >> 2;
    const int hp = rem & 3;

    const __half* Pq = branch ? P2 : P1;
    const __half* Pkv = branch ? P1 : P2;
    const int boff = branch << 8;
    const int base = b * 4096 + (axis ? x * 64 : x);
    const int step = axis ? 1 : 64;

    // ---- load 64 tokens x 64 halfs (2 heads) for q, k, v ----
    {
        const int lrow = tid >> 2;
        const int lseg = (tid & 3) << 4;
        size_t trow = (size_t)(base + lrow * step) * 768;
        const uint4* qp = (const uint4*)(Pq + trow + hp * 64 + lseg);
        *(uint4*)&qs[lrow][lseg] = qp[0];
        *(uint4*)&qs[lrow][lseg + 8] = qp[1];
        const uint4* kp = (const uint4*)(Pkv + trow + 256 + hp * 64 + lseg);
        *(uint4*)&ks[lrow][lseg] = kp[0];
        *(uint4*)&ks[lrow][lseg + 8] = kp[1];
        const uint4* vp = (const uint4*)(Pkv + trow + 512 + hp * 64 + lseg);
        *(uint4*)&vs[lrow][lseg] = vp[0];
        *(uint4*)&vs[lrow][lseg + 8] = vp[1];
    }
    __syncthreads();

    const int hl = warp >> 2;     // head within pair
    const int mb = warp & 3;      // row block
    const int hq = hl << 5;       // smem col base
    const int r1 = mb * 16 + g;
    const int r2 = r1 + 8;

    // ldmatrix lane-address components
    const int arow = (lane & 15);
    const int acol = ((lane >> 4) << 3);
    const int brow = ((lane >> 4) << 3) + (lane & 7);
    const int bcol = (((lane >> 3) & 1) << 3);

    // ---- S = Q @ K^T  (fp32 accum) ----
    uint32_t a[2][4];
#pragma unroll
    for (int kk = 0; kk < 2; kk++) {
        uint32_t addr = smem_u32(&qs[mb * 16 + arow][hq + (kk << 4) + acol]);
        LDMX4(a[kk][0], a[kk][1], a[kk][2], a[kk][3], addr);
    }
    float sc[8][4];
#pragma unroll
    for (int nt = 0; nt < 8; nt++)
#pragma unroll
        for (int u = 0; u < 4; u++) sc[nt][u] = 0.f;
#pragma unroll
    for (int p = 0; p < 4; p++) {
#pragma unroll
        for (int kk = 0; kk < 2; kk++) {
            uint32_t addr = smem_u32(&ks[(p << 4) + brow][hq + (kk << 4) + bcol]);
            uint32_t r0, r1u, r2u, r3;
            LDMX4(r0, r1u, r2u, r3, addr);
            mma_f16(sc[2 * p], a[kk], r0, r1u);
            mma_f16(sc[2 * p + 1], a[kk], r2u, r3);
        }
    }

    // ---- softmax over 64 cols (rows r1, r2) ----
    float mx1 = -1e30f, mx2 = -1e30f;
#pragma unroll
    for (int nt = 0; nt < 8; nt++) {
        mx1 = fmaxf(mx1, fmaxf(sc[nt][0], sc[nt][1]));
        mx2 = fmaxf(mx2, fmaxf(sc[nt][2], sc[nt][3]));
    }
    mx1 = fmaxf(mx1, __shfl_xor_sync(0xffffffffu, mx1, 1));
    mx1 = fmaxf(mx1, __shfl_xor_sync(0xffffffffu, mx1, 2));
    mx2 = fmaxf(mx2, __shfl_xor_sync(0xffffffffu, mx2, 1));
    mx2 = fmaxf(mx2, __shfl_xor_sync(0xffffffffu, mx2, 2));

    const float cexp = 0.17677669529663687f * 1.4426950408889634f;
    float s1 = 0.f, s2 = 0.f;
#pragma unroll
    for (int nt = 0; nt < 8; nt++) {
        sc[nt][0] = fexp2((sc[nt][0] - mx1) * cexp);
        sc[nt][1] = fexp2((sc[nt][1] - mx1) * cexp);
        sc[nt][2] = fexp2((sc[nt][2] - mx2) * cexp);
        sc[nt][3] = fexp2((sc[nt][3] - mx2) * cexp);
        s1 += sc[nt][0] + sc[nt][1];
        s2 += sc[nt][2] + sc[nt][3];
    }
    s1 += __shfl_xor_sync(0xffffffffu, s1, 1);
    s1 += __shfl_xor_sync(0xffffffffu, s1, 2);
    s2 += __shfl_xor_sync(0xffffffffu, s2, 1);
    s2 += __shfl_xor_sync(0xffffffffu, s2, 2);
    const float inv1 = 1.0f / s1;
    const float inv2 = 1.0f / s2;

    // ---- O = P @ V  (P fragments reused in-register, V via ldmatrix.trans) ----
    float od[4][4];
#pragma unroll
    for (int nt2 = 0; nt2 < 4; nt2++)
#pragma unroll
        for (int u = 0; u < 4; u++) od[nt2][u] = 0.f;

#pragma unroll
    for (int ks2 = 0; ks2 < 4; ks2++) {
        uint32_t pa[4];
        {
            __half2 h;
            h = __floats2half2_rn(sc[2 * ks2][0], sc[2 * ks2][1]);
            pa[0] = *(uint32_t*)&h;
            h = __floats2half2_rn(sc[2 * ks2][2], sc[2 * ks2][3]);
            pa[1] = *(uint32_t*)&h;
            h = __floats2half2_rn(sc[2 * ks2 + 1][0], sc[2 * ks2 + 1][1]);
            pa[2] = *(uint32_t*)&h;
            h = __floats2half2_rn(sc[2 * ks2 + 1][2], sc[2 * ks2 + 1][3]);
            pa[3] = *(uint32_t*)&h;
        }
        const int k0 = ks2 << 4;
#pragma unroll
        for (int pp = 0; pp < 2; pp++) {
            // ldmatrix.x4.trans: mats = (k0..k0+15) x cols {d0, d0+8}
            int vrow = k0 + (lane & 15);
            int vcol = hq + (pp << 4) + ((lane >> 4) << 3);
            uint32_t addr = smem_u32(&vs[vrow][vcol]);
            uint32_t v0, v1, v2, v3;
            asm volatile(
                "ldmatrix.sync.aligned.m8n8.x4.trans.shared.b16 {%0,%1,%2,%3}, [%4];"
                : "=r"(v0), "=r"(v1), "=r"(v2), "=r"(v3) : "r"(addr));
            mma_f16(od[2 * pp], pa, v0, v1);
            mma_f16(od[2 * pp + 1], pa, v2, v3);
        }
    }

    // ---- write O ----
    const size_t t1 = (size_t)(base + r1 * step);
    const size_t t2 = (size_t)(base + r2 * step);
    const int colb = boff + (hp << 6) + (hl << 5) + 2 * t4;
#pragma unroll
    for (int nt2 = 0; nt2 < 4; nt2++) {
        int col = colb + nt2 * 8;
        __half2* p1o = (__half2*)&O[t1 * 512 + col];
        __half2* p2o = (__half2*)&O[t2 * 512 + col];
        float c0 = od[nt2][0] * inv1, c1 = od[nt2][1] * inv1;
        float c2 = od[nt2][2] * inv2, c3 = od[nt2][3] * inv2;
        if (axis == 0) {
            *p1o = __floats2half2_rn(c0, c1);
            *p2o = __floats2half2_rn(c2, c3);
        } else {
            float2 f1 = __half22float2(*p1o);
            float2 f2 = __half22float2(*p2o);
            *p1o = __floats2half2_rn(f1.x + c0, f1.y + c1);
            *p2o = __floats2half2_rn(f2.x + c2, f2.y + c3);
        }
    }
}

// ---------------------------------------------------------------------------
// Final transpose + x2 residual: out = transpose(acc) + x2 (both NCHW-coalesced)
// ---------------------------------------------------------------------------
__global__ void transpose_out_kernel(const float* __restrict__ acc,
                                     const float* __restrict__ x2,
                                     float* __restrict__ out) {
    __shared__ float t[32][33];
    int b = blockIdx.z;
    int hw0 = blockIdx.x * 32;
    int c0 = blockIdx.y * 32;
    int tx = threadIdx.x, ty = threadIdx.y;
#pragma unroll
    for (int q = 0; q < 4; q++)
        t[ty + q * 8][tx] =
            acc[((size_t)b * 4096 + hw0 + ty + q * 8) * 256 + c0 + tx];
    __syncthreads();
#pragma unroll
    for (int q = 0; q < 4; q++) {
        size_t oi = (((size_t)(b * 256 + c0 + ty + q * 8)) << 12) + hw0 + tx;
        out[oi] = t[tx][ty + q * 8] + x2[oi];
    }
}

// ---------------------------------------------------------------------------
// Launch
// ---------------------------------------------------------------------------
extern "C" void kernel_launch(void* const* d_in, const int* in_sizes, int n_in,
                              void* d_out, int out_size) {
    const float* x1     = (const float*)d_in[0];
    const float* x2     = (const float*)d_in[1];
    const float* ln1q_w = (const float*)d_in[2];
    const float* ln1q_b = (const float*)d_in[3];
    const float* ln2kv_w= (const float*)d_in[4];
    const float* ln2kv_b= (const float*)d_in[5];
    const float* Wq1    = (const float*)d_in[6];
    const float* Wkv2   = (const float*)d_in[7];
    const float* Wout1  = (const float*)d_in[8];
    const float* bout1  = (const float*)d_in[9];
    const float* ln2q_w = (const float*)d_in[10];
    const float* ln2q_b = (const float*)d_in[11];
    const float* ln1kv_w= (const float*)d_in[12];
    const float* ln1kv_b= (const float*)d_in[13];
    const float* Wq2    = (const float*)d_in[14];
    const float* Wkv1   = (const float*)d_in[15];
    const float* Wout2  = (const float*)d_in[16];
    const float* bout2  = (const float*)d_in[17];
    const float* Wsc    = (const float*)d_in[18];
    const float* bng    = (const float*)d_in[19];
    const float* bnb    = (const float*)d_in[20];
    const float* bnm    = (const float*)d_in[21];
    const float* bnv    = (const float*)d_in[22];
    float* out = (float*)d_out;

    float* S = nullptr;
    cudaGetSymbolAddress((void**)&S, g_scratch);
    float* mu1  = S + OFF_MU1;  float* rs1 = S + OFF_RS1;
    float* mu2  = S + OFF_MU2;  float* rs2 = S + OFF_RS2;
    __half* A1h = (__half*)(S + OFF_A1H);
    __half* A2h = (__half*)(S + OFF_A2H);
    __half* B1h = (__half*)(S + OFF_B1H);
    __half* B2h = (__half*)(S + OFF_B2H);
    __half* BscH= (__half*)(S + OFF_BSCH);
    __half* BoCH= (__half*)(S + OFF_BOCH);
    float* vb1  = S + OFF_VB1;  float* vb2 = S + OFF_VB2;
    float* vboc = S + OFF_VBOC; float* vbsc= S + OFF_VBSC;
    float* wsum = S + OFF_WSUM;
    __half* P1h = (__half*)(S + OFF_P1);
    __half* P2h = (__half*)(S + OFF_P2);
    __half* Oh  = (__half*)(S + OFF_OH);
    float* accb = S + OFF_ACC;

    dim3 tb(32, 8);

    // 1) stats + normalized-A preps (half)
    ln_stats_kernel<<<NTOK / 256, 256>>>(x1, DIM1, mu1, rs1);
    ln_stats_kernel<<<NTOK / 256, 256>>>(x2, DIM2, mu2, rs2);
    prep_a_kernel<<<dim3(128, 12, 8), tb>>>(x1, DIM1, mu1, rs1, A1h);
    prep_a_kernel<<<dim3(128, 8, 8), tb>>>(x2, DIM2, mu2, rs2, A2h);

    // 2) weight preps: B1h = [q1|kv1] (K=384), B2h = [q2|kv2] (K=256),
    //    BoCH = [Wout1;Wout2] (N=256, K=512)
    prep_w_kernel<<<dim3(12, 8), tb>>>(Wq1, 384, 256, ln1q_w, B1h, 384, 0);
    prep_w_kernel<<<dim3(12, 16), tb>>>(Wkv1, 384, 512, ln1kv_w, B1h + 256 * 384, 384, 0);
    prep_w_kernel<<<dim3(8, 8), tb>>>(Wq2, 256, 256, ln2q_w, B2h, 256, 0);
    prep_w_kernel<<<dim3(8, 16), tb>>>(Wkv2, 256, 512, ln2kv_w, B2h + 256 * 256, 256, 0);
    prep_w_kernel<<<dim3(8, 8), tb>>>(Wout1, 256, 256, nullptr, BoCH, 512, 0);
    prep_w_kernel<<<dim3(8, 8), tb>>>(Wout2, 256, 256, nullptr, BoCH, 512, 256);
    prep_wsc_kernel<<<384, 256>>>(Wsc, bng, bnv, BscH);
    prep_bias_kernel<<<1, 256>>>(Wq1, 384, 256, ln1q_b, vb1);
    prep_bias_kernel<<<2, 256>>>(Wkv1, 384, 512, ln1kv_b, vb1 + 256);
    prep_bias_kernel<<<1, 256>>>(Wq2, 256, 256, ln2q_b, vb2);
    prep_bias_kernel<<<2, 256>>>(Wkv2, 256, 512, ln2kv_b, vb2 + 256);
    prep_sc_bias_kernel<<<1, 256>>>(Wsc, bng, bnb, bnm, bnv, vbsc, wsum);
    prep_vboc_kernel<<<1, 256>>>(bout1, bout2, vboc);

    // 3) fused projections (half in, half out)
    hgemm<0><<<dim3(6, 256), 256>>>(A1h, B1h, P1h, 384, 768, vb1,
                                    nullptr, nullptr, nullptr);
    hgemm<0><<<dim3(6, 256), 256>>>(A2h, B2h, P2h, 256, 768, vb2,
                                    nullptr, nullptr, nullptr);

    // 4) shortcut GEMM -> acc = BN(x1f@Wsc^T)  (x2 residual moved to transpose)
    hgemm<1><<<dim3(2, 256), 256>>>(A1h, BscH, accb, 384, 256, vbsc,
                                    mu1, rs1, wsum);

    // 5) mma axial attention: axis0 writes O, axis1 accumulates
    attn_mma_kernel<<<4096, 256>>>(P1h, P2h, Oh, 0);
    attn_mma_kernel<<<4096, 256>>>(P1h, P2h, Oh, 1);

    // 6) combined output projection: acc += [o1|o2] @ [Wout1;Wout2] + biases
    hgemm<2><<<dim3(2, 256), 256>>>(Oh, BoCH, accb, 512, 256, vboc,
                                    nullptr, nullptr, nullptr);

    // 7) NHWC -> NCHW with fused x2 residual
    transpose_out_kernel<<<dim3(128, 8, 8), tb>>>(accb, x2, out);
}